// round 14
// baseline (speedup 1.0000x reference)
#include <cuda_runtime.h>
#include <math.h>
#include <stdint.h>

// Problem constants
#define TLEN 4096
#define BSZ 8

typedef unsigned long long ull;

// Packed fp32x2 helpers
#define FMA2(acc, a, b) \
    asm("fma.rn.f32x2 %0, %1, %2, %3;" : "=l"(acc) : "l"(a), "l"(b), "l"(acc))
#define PACKB(d, s) \
    asm("mov.b64 %0, {%1, %1};" : "=l"(d) : "f"(s))
#define PACK2(d, lo, hi) \
    asm("mov.b64 %0, {%1, %2};" : "=l"(d) : "f"(lo), "f"(hi))
#define UNPACK2(lo, hi, s) \
    asm("mov.b64 {%0, %1}, %2;" : "=f"(lo), "=f"(hi) : "l"(s))

// cp.async primitives
__device__ __forceinline__ void cp4(uint32_t dst, const float* src, bool ok) {
    int sz = ok ? 4 : 0;
    asm volatile("cp.async.ca.shared.global [%0], [%1], 4, %2;"
                 :: "r"(dst), "l"(src), "r"(sz));
}
__device__ __forceinline__ void cp16(uint32_t dst, const void* src) {
    asm volatile("cp.async.cg.shared.global [%0], [%1], 16;"
                 :: "r"(dst), "l"(src));
}
#define CP_COMMIT() asm volatile("cp.async.commit_group;")
#define CP_WAIT(N) asm volatile("cp.async.wait_group %0;" :: "n"(N))

__device__ __forceinline__ int swz(int c) { return c ^ ((c >> 3) & 3); }
__device__ __forceinline__ int swzf(int p) { return (swz(p >> 2) << 2) | (p & 3); }

__device__ __forceinline__ uint32_t smem_u32(const void* p) {
    return (uint32_t)__cvta_generic_to_shared(p);
}

// ---------------- device scratch ----------------
__device__ float g_x2[BSZ * 128 * TLEN];
__device__ float g_x3[BSZ * 256 * TLEN];
__device__ float g_x4[BSZ * 512 * TLEN];
__device__ float g_x5[BSZ * 512 * TLEN];
__device__ float g_w2T[64 * 5 * 128];
__device__ float g_w3T[128 * 5 * 256];
__device__ float g_w4T[256 * 3 * 512];
__device__ float g_w5T[512 * 3 * 512];
__device__ float g_hwT[512 * 256];
__device__ float g_cnorm[8 * 1024];
__device__ float g_L[8 * 1024 * 256];
__device__ float g_part[2048];
__device__ int g_qhead;
__device__ int g_done[5][8][32];

#define OFF_A 0
#define OFF_B (BSZ * 8 * TLEN)
#define OFF_L (OFF_B + BSZ * 4 * TLEN * 64)

// queue layout
#define Q_L1 256
#define Q_L2 768
#define Q_L3 1792
#define Q_L4 2816
#define Q_L5 4864
#define Q_END 5888

// ---------------- prep (proven) ----------------
__device__ __forceinline__ void tr_seg(int local, const float* __restrict__ w,
                                       float* __restrict__ wT, int CIN, int COUT, int K) {
    int co = local % COUT;
    int j = (local / COUT) % K;
    int ci = local / (COUT * K);
    wT[local] = w[((size_t)co * CIN + ci) * K + j];
}
#define N_W2 (64 * 5 * 128)
#define N_W3 (128 * 5 * 256)
#define N_W4 (256 * 3 * 512)
#define N_W5 (512 * 3 * 512)
#define N_HW (512 * 256)
#define N_CN (8 * 1024)
#define N_PREP (N_W2 + N_W3 + N_W4 + N_W5 + N_HW + N_CN)

__global__ void prep_kernel(const float* __restrict__ w2, const float* __restrict__ w3,
                            const float* __restrict__ w4, const float* __restrict__ w5,
                            const float* __restrict__ hw, const float* __restrict__ cbk,
                            float* __restrict__ w2T, float* __restrict__ w3T,
                            float* __restrict__ w4T, float* __restrict__ w5T,
                            float* __restrict__ hwT, float* __restrict__ cnorm) {
    int i = blockIdx.x * 256 + threadIdx.x;
    if (i < N_W2) { tr_seg(i, w2, w2T, 64, 128, 5); return; }
    i -= N_W2;
    if (i < N_W3) { tr_seg(i, w3, w3T, 128, 256, 5); return; }
    i -= N_W3;
    if (i < N_W4) { tr_seg(i, w4, w4T, 256, 512, 3); return; }
    i -= N_W4;
    if (i < N_W5) { tr_seg(i, w5, w5T, 512, 512, 3); return; }
    i -= N_W5;
    if (i < N_HW) {
        int co = i % 256, d = i / 256;
        int h = co >> 6, v = co & 63;
        hwT[i] = hw[((size_t)h * 512 + d) * 64 + v];
        return;
    }
    i -= N_HW;
    if (i < N_CN) {
        const float* row = cbk + (size_t)i * 64;
        float s = 0.f;
#pragma unroll 8
        for (int d = 0; d < 64; d++) { float v = row[d]; s += v * v; }
        cnorm[i] = s;
    }
}

__global__ void reset_kernel() {
    int i = blockIdx.x * 256 + threadIdx.x;
    if (i == 0) g_qhead = 0;
    if (i < 5 * 8 * 32) ((int*)g_done)[i] = 0;
}

// ------- code-logits table (proven) -------
__global__ __launch_bounds__(256)
void codelogits_kernel(const float* __restrict__ cbk, const float* __restrict__ hwT,
                       float* __restrict__ L) {
    extern __shared__ float smc[];
    float* sct = smc;
    float* sw = smc + 64 * 132;
    const int k0 = blockIdx.x * 128;
    const int co0 = blockIdx.y * 128;
    const int g = blockIdx.z;
    const int tid = threadIdx.x;
    const int tx = tid & 15, ty = tid >> 4;
    const int kb = tx * 8, cb = ty * 8;

    for (int i = tid; i < 8192; i += 256) {
        int k = i >> 6, d = i & 63;
        sct[d * 132 + k] = cbk[((size_t)g * 1024 + k0 + k) * 64 + d];
    }
    for (int i = tid; i < 8192; i += 256) {
        int d = i >> 7, co = i & 127;
        sw[d * 132 + co] = hwT[((size_t)(g * 64 + d)) * 256 + co0 + co];
    }
    __syncthreads();

    float acc[8][8];
#pragma unroll
    for (int a = 0; a < 8; a++)
#pragma unroll
        for (int c = 0; c < 8; c++) acc[a][c] = 0.f;

#pragma unroll 4
    for (int d = 0; d < 64; d++) {
        float kk[8], ww[8];
        *(float4*)&kk[0] = *(const float4*)&sct[d * 132 + kb];
        *(float4*)&kk[4] = *(const float4*)&sct[d * 132 + kb + 4];
        *(float4*)&ww[0] = *(const float4*)&sw[d * 132 + cb];
        *(float4*)&ww[4] = *(const float4*)&sw[d * 132 + cb + 4];
#pragma unroll
        for (int a = 0; a < 8; a++)
#pragma unroll
            for (int c = 0; c < 8; c++) acc[a][c] = fmaf(kk[a], ww[c], acc[a][c]);
    }

#pragma unroll
    for (int a = 0; a < 8; a++) {
        float* base = L + ((size_t)g * 1024 + k0 + kb + a) * 256 + co0 + cb;
        *(float4*)base = *(float4*)&acc[a][0];
        *(float4*)(base + 4) = *(float4*)&acc[a][4];
    }
}

// ================= tile bodies (bitwise identical math) =================

// ---- conv12 tile ----
#define C12_XROW 136
#define C12_AUD 0
#define C12_W1 144
#define C12_B1 (144 + 448)
#define C12_X1 (144 + 448 + 64)
#define C12_WS (C12_X1 + 64 * C12_XROW)

__device__ void tile_conv12(const float* __restrict__ audio, const float* __restrict__ w1,
                            const float* __restrict__ b1, const float* __restrict__ wT,
                            const float* __restrict__ bias, float* __restrict__ y,
                            int b, int t0, float* smem) {
    constexpr int K = 5, COUT = 128, CI_CHUNK = 8;
    constexpr int NX = 12, NXF4 = 3;
    constexpr int WS_FL = CI_CHUNK * K * 128;
    constexpr int NCHUNK = 8;

    const uint32_t sb = smem_u32(smem);
    float* audio_s = smem + C12_AUD;
    float* w1s = smem + C12_W1;
    float* b1s = smem + C12_B1;
    float* x1s = smem + C12_X1;
    const int tid = threadIdx.x;
    const int tx = tid & 15, ty = tid >> 4;
    const int tb = tx * 8, cb = ty * 8;

    auto loadW = [&](int c, int st) {
        uint32_t wbB = sb + (uint32_t)(C12_WS + st * WS_FL) * 4u;
        const int ci0 = c * CI_CHUNK;
        for (int i4 = tid * 4; i4 < WS_FL; i4 += 1024) {
            int cc = i4 / (K * 128);
            int rem = i4 % (K * 128);
            int j = rem / 128, co = rem % 128;
            cp16(wbB + (uint32_t)i4 * 4u,
                 wT + ((size_t)(ci0 + cc) * K + j) * COUT + co);
        }
        CP_COMMIT();
    };

    for (int i = tid; i < 138; i += 256) {
        int t = t0 - 10 + i;
        cp4(sb + (uint32_t)(C12_AUD + i) * 4u,
            audio + (size_t)b * TLEN + (t >= 0 ? t : 0), t >= 0);
    }
    for (int i4 = tid * 4; i4 < 448; i4 += 1024)
        cp16(sb + (uint32_t)(C12_W1 + i4) * 4u, w1 + i4);
    if (tid < 16)
        cp16(sb + (uint32_t)(C12_B1 + tid * 4) * 4u, b1 + tid * 4);
    CP_COMMIT();
    loadW(0, 0);
    loadW(1, 1);

    CP_WAIT(2);
    __syncthreads();

    for (int i = tid; i < 64 * 132; i += 256) {
        int ch = i / 132, p = i % 132;
        int t = t0 - 4 + p;
        float v = 0.f;
        if (t >= 0) {
            float acc = b1s[ch];
#pragma unroll
            for (int j = 0; j < 7; j++) acc += w1s[ch * 7 + j] * audio_s[p + j];
            v = acc > 0.f ? acc : expm1f(acc);
        }
        x1s[ch * C12_XROW + swzf(p)] = v;
    }
    __syncthreads();

    ull acc2[4][8];
#pragma unroll
    for (int rp = 0; rp < 4; rp++) {
        ull bb2;
        PACK2(bb2, bias[cb + 2 * rp], bias[cb + 2 * rp + 1]);
#pragma unroll
        for (int lt = 0; lt < 8; lt++) acc2[rp][lt] = bb2;
    }

    int st = 0;
#pragma unroll 1
    for (int c = 0; c < NCHUNK; c++) {
        if (c + 1 < NCHUNK) { CP_WAIT(1); } else { CP_WAIT(0); }
        __syncthreads();
        if (c + 2 < NCHUNK) {
            int st2 = st + 2; if (st2 >= 3) st2 -= 3;
            loadW(c + 2, st2);
        }
        const float* wsb = smem + C12_WS + st * WS_FL;
        const float* xbase = x1s + c * CI_CHUNK * C12_XROW;
#pragma unroll 1
        for (int cc = 0; cc < CI_CHUNK; cc++) {
            const float* xrow = xbase + cc * C12_XROW;
            float xv[NXF4 * 4];
#pragma unroll
            for (int q = 0; q < NXF4; q++)
                *(float4*)&xv[q * 4] = *(const float4*)&xrow[swz(tx * 2 + q) << 2];
            ull xb[NX];
#pragma unroll
            for (int p = 0; p < NX; p++) PACKB(xb[p], xv[p]);
#pragma unroll
            for (int j = 0; j < K; j++) {
                const float* wrow = wsb + (cc * K + j) * 128 + cb;
                ulonglong2 w01 = *(const ulonglong2*)&wrow[0];
                ulonglong2 w23 = *(const ulonglong2*)&wrow[4];
                ull wp[4] = {w01.x, w01.y, w23.x, w23.y};
#pragma unroll
                for (int rp = 0; rp < 4; rp++)
#pragma unroll
                    for (int lt = 0; lt < 8; lt++)
                        FMA2(acc2[rp][lt], wp[rp], xb[lt + j]);
            }
        }
        if (++st == 3) st = 0;
    }

    float accs[8][8];
#pragma unroll
    for (int rp = 0; rp < 4; rp++)
#pragma unroll
        for (int lt = 0; lt < 8; lt++)
            UNPACK2(accs[2 * rp][lt], accs[2 * rp + 1][lt], acc2[rp][lt]);

#pragma unroll
    for (int r = 0; r < 8; r++) {
        float o[8];
#pragma unroll
        for (int lt = 0; lt < 8; lt++) {
            float a = accs[r][lt];
            o[lt] = a > 0.f ? a : expm1f(a);
        }
        float* base = &y[((size_t)b * COUT + cb + r) * TLEN + t0 + tb];
        *(float4*)base = *(float4*)&o[0];
        *(float4*)(base + 4) = *(float4*)&o[4];
    }
}

// ---- generic conv tile ----
template <int CIN, int COUT, int K, int CI_CHUNK, int ELU>
__device__ void tile_conv(const float* __restrict__ x, const float* __restrict__ wT,
                          const float* __restrict__ bias, float* __restrict__ y,
                          int b, int t0, int co0, float* smem) {
    constexpr int XROW = 136;
    constexpr int NX = 8 + K - 1;
    constexpr int NXF4 = (NX + 3) / 4;
    constexpr int XS_FL = CI_CHUNK * XROW;
    constexpr int WS_FL = CI_CHUNK * K * 128;
    constexpr int STG_FL = XS_FL + WS_FL;
    constexpr int NCHUNK = CIN / CI_CHUNK;

    const uint32_t sb = smem_u32(smem);
    const int tid = threadIdx.x;
    const int tx = tid & 15, ty = tid >> 4;
    const int tb = tx * 8, cb = ty * 8;

    auto load_chunk = [&](int c, int st) {
        const int ci0 = c * CI_CHUNK;
        uint32_t xbB = sb + (uint32_t)(st * STG_FL) * 4u;
        for (int i = tid; i < XS_FL; i += 256) {
            int cc = i / XROW, p = i % XROW;
            int t = t0 - (K - 1) + p;
            bool ok = (t >= 0) && (t < TLEN);
            const float* src = x + ((size_t)b * CIN + ci0 + cc) * TLEN + (ok ? t : 0);
            cp4(xbB + (uint32_t)(cc * XROW + swzf(p)) * 4u, src, ok);
        }
        uint32_t wbB = xbB + (uint32_t)XS_FL * 4u;
        for (int i4 = tid * 4; i4 < WS_FL; i4 += 1024) {
            int cc = i4 / (K * 128);
            int rem = i4 % (K * 128);
            int j = rem / 128, co = rem % 128;
            cp16(wbB + (uint32_t)i4 * 4u,
                 wT + ((size_t)(ci0 + cc) * K + j) * COUT + co0 + co);
        }
        CP_COMMIT();
    };

    load_chunk(0, 0);
    if (NCHUNK > 1) load_chunk(1, 1);

    ull acc2[4][8];
#pragma unroll
    for (int rp = 0; rp < 4; rp++) {
        ull bb2;
        PACK2(bb2, bias[co0 + cb + 2 * rp], bias[co0 + cb + 2 * rp + 1]);
#pragma unroll
        for (int lt = 0; lt < 8; lt++) acc2[rp][lt] = bb2;
    }

    int st = 0;
#pragma unroll 1
    for (int c = 0; c < NCHUNK; c++) {
        if (c + 1 < NCHUNK) { CP_WAIT(1); } else { CP_WAIT(0); }
        __syncthreads();
        if (c + 2 < NCHUNK) {
            int st2 = st + 2; if (st2 >= 3) st2 -= 3;
            load_chunk(c + 2, st2);
        }
        const float* xsb = smem + st * STG_FL;
        const float* wsb = xsb + XS_FL;
#pragma unroll 1
        for (int cc = 0; cc < CI_CHUNK; cc++) {
            const float* xrow = xsb + cc * XROW;
            float xv[NXF4 * 4];
#pragma unroll
            for (int q = 0; q < NXF4; q++)
                *(float4*)&xv[q * 4] = *(const float4*)&xrow[swz(tx * 2 + q) << 2];
            ull xb[NX];
#pragma unroll
            for (int p = 0; p < NX; p++) PACKB(xb[p], xv[p]);
#pragma unroll
            for (int j = 0; j < K; j++) {
                const float* wrow = wsb + (cc * K + j) * 128 + cb;
                ulonglong2 w01 = *(const ulonglong2*)&wrow[0];
                ulonglong2 w23 = *(const ulonglong2*)&wrow[4];
                ull wp[4] = {w01.x, w01.y, w23.x, w23.y};
#pragma unroll
                for (int rp = 0; rp < 4; rp++)
#pragma unroll
                    for (int lt = 0; lt < 8; lt++)
                        FMA2(acc2[rp][lt], wp[rp], xb[lt + j]);
            }
        }
        if (++st == 3) st = 0;
    }

    float accs[8][8];
#pragma unroll
    for (int rp = 0; rp < 4; rp++)
#pragma unroll
        for (int lt = 0; lt < 8; lt++)
            UNPACK2(accs[2 * rp][lt], accs[2 * rp + 1][lt], acc2[rp][lt]);

#pragma unroll
    for (int r = 0; r < 8; r++) {
        float o[8];
#pragma unroll
        for (int lt = 0; lt < 8; lt++) {
            float a = accs[r][lt];
            if (ELU) a = a > 0.f ? a : expm1f(a);
            o[lt] = a;
        }
        float* base = &y[((size_t)b * COUT + co0 + cb + r) * TLEN + t0 + tb];
        *(float4*)base = *(float4*)&o[0];
        *(float4*)(base + 4) = *(float4*)&o[4];
    }
}

// ---- VQ tile ----
#define VQ_ZT 0
#define VQ_CB0 8192
#define VQ_CB1 (8192 + 8448)
#define VQ_CNORM (8192 + 16896)
#define VQ_ZN (VQ_CNORM + 1024)
#define VQ_BI (VQ_ZN + 128)
#define VQ_FLOATS (VQ_BI + 128)
#define VQ_BYTES (VQ_FLOATS * 4)
#define VQ_RV VQ_CB0
#define VQ_RI (VQ_CB0 + 2048)
#define VQ_LS VQ_CNORM

__device__ void tile_vq(const float* __restrict__ x5, const float* __restrict__ cbk,
                        const float* __restrict__ cnormG,
                        float* __restrict__ out_a, float* __restrict__ partial,
                        int b, int g, int tbi, float* smem) {
    const uint32_t sb = smem_u32(smem);
    float* ztT = smem + VQ_ZT;
    float* cnormS = smem + VQ_CNORM;
    float* znorm = smem + VQ_ZN;
    int* besti = (int*)(smem + VQ_BI);
    float* redv = smem + VQ_RV;
    int* redi = (int*)(smem + VQ_RI);
    float* lscr = smem + VQ_LS;

    const int t0 = tbi * 128;
    const int tid = threadIdx.x;
    const int tx = tid & 15, ty = tid >> 4;
    const int trow = tx * 8, cbase = ty * 8;

    for (int i = tid; i < 8192; i += 256) {
        int d = i >> 7, lt = i & 127;
        cp4(sb + (uint32_t)(VQ_ZT + d * 128 + swzf(lt)) * 4u,
            x5 + (((size_t)b * 512) + (g << 6) + d) * TLEN + t0 + lt, true);
    }
    cp16(sb + (uint32_t)(VQ_CNORM + tid * 4) * 4u, cnormG + g * 1024 + tid * 4);
    for (int i = tid; i < 8192; i += 256) {
        int kk = i >> 6, d = i & 63;
        cp4(sb + (uint32_t)(VQ_CB0 + d * 132 + kk) * 4u,
            cbk + ((size_t)g * 1024 + kk) * 64 + d, true);
    }
    CP_COMMIT();

    float zn[8], bv[8];
    int bi8[8];
#pragma unroll
    for (int a = 0; a < 8; a++) { bv[a] = 3.4e38f; bi8[a] = 0; }

#pragma unroll 1
    for (int c = 0; c < 8; c++) {
        const int k0 = c << 7;
        if (c + 1 < 8) {
            const int koff = (c + 1) << 7;
            uint32_t cbB = sb + (uint32_t)(((c + 1) & 1) ? VQ_CB1 : VQ_CB0) * 4u;
            for (int i = tid; i < 8192; i += 256) {
                int kk = i >> 6, d = i & 63;
                cp4(cbB + (uint32_t)(d * 132 + kk) * 4u,
                    cbk + ((size_t)g * 1024 + koff + kk) * 64 + d, true);
            }
            CP_COMMIT();
            CP_WAIT(1);
        } else {
            CP_WAIT(0);
        }
        __syncthreads();

        if (c == 0) {
            if (tid < 128) {
                float s = 0.f;
                int off = swzf(tid);
#pragma unroll 8
                for (int d = 0; d < 64; d++) { float v = ztT[d * 128 + off]; s += v * v; }
                znorm[tid] = s;
            }
            __syncthreads();
#pragma unroll
            for (int a = 0; a < 8; a++) zn[a] = znorm[trow + a];
        }

        const float* ct = smem + ((c & 1) ? VQ_CB1 : VQ_CB0);
        ull acc2[8][4];
#pragma unroll
        for (int a = 0; a < 8; a++)
#pragma unroll
            for (int q = 0; q < 4; q++) acc2[a][q] = 0ull;

#pragma unroll 4
        for (int d = 0; d < 64; d++) {
            float zz[8];
            *(float4*)&zz[0] = *(const float4*)&ztT[d * 128 + (swz(tx * 2) << 2)];
            *(float4*)&zz[4] = *(const float4*)&ztT[d * 128 + (swz(tx * 2 + 1) << 2)];
            ull zb[8];
#pragma unroll
            for (int a = 0; a < 8; a++) PACKB(zb[a], zz[a]);
            ulonglong2 c01 = *(const ulonglong2*)&ct[d * 132 + cbase];
            ulonglong2 c23 = *(const ulonglong2*)&ct[d * 132 + cbase + 4];
            ull cp_[4] = {c01.x, c01.y, c23.x, c23.y};
#pragma unroll
            for (int a = 0; a < 8; a++)
#pragma unroll
                for (int q = 0; q < 4; q++)
                    FMA2(acc2[a][q], zb[a], cp_[q]);
        }

        float accs[8][8];
#pragma unroll
        for (int a = 0; a < 8; a++)
#pragma unroll
            for (int q = 0; q < 4; q++)
                UNPACK2(accs[a][2 * q], accs[a][2 * q + 1], acc2[a][q]);

        float cn[8];
#pragma unroll
        for (int cc = 0; cc < 8; cc++) cn[cc] = cnormS[k0 + cbase + cc];
#pragma unroll
        for (int a = 0; a < 8; a++) {
#pragma unroll
            for (int cc = 0; cc < 8; cc++) {
                float dist = zn[a] + cn[cc] - 2.f * accs[a][cc];
                int idx = k0 + cbase + cc;
                if (dist < bv[a]) { bv[a] = dist; bi8[a] = idx; }
            }
        }
        __syncthreads();
    }

#pragma unroll
    for (int a = 0; a < 8; a++) {
        int tok = trow + a;
        redv[tok * 16 + ty] = bv[a];
        redi[tok * 16 + ty] = bi8[a];
    }
    __syncthreads();
    if (tid < 128) {
        float best = redv[tid * 16];
        int bidx = redi[tid * 16];
#pragma unroll
        for (int s = 1; s < 16; s++) {
            float v = redv[tid * 16 + s];
            int ii = redi[tid * 16 + s];
            if (v < best || (v == best && ii < bidx)) { best = v; bidx = ii; }
        }
        besti[tid] = bidx;
        out_a[((size_t)b * 8 + g) * TLEN + t0 + tid] = (float)bidx;
    }
    __syncthreads();

    float ls = 0.f;
    for (int i = tid; i < 64 * 128; i += 256) {
        int d = i & 63, lt = i >> 6;
        float qv = cbk[((size_t)g * 1024 + besti[lt]) * 64 + d];
        float df = qv - ztT[d * 128 + swzf(lt)];
        ls += df * df;
    }
    lscr[tid] = ls;
    __syncthreads();
    for (int s = 128; s > 0; s >>= 1) {
        if (tid < s) lscr[tid] += lscr[tid + s];
        __syncthreads();
    }
    if (tid == 0)
        partial[((size_t)b * 8 + g) * 32 + tbi] = lscr[0];
}

// ---- logits gather tile ----
__device__ void tile_glogits(const float* __restrict__ outA, const float* __restrict__ L,
                             const float* __restrict__ head_b, float* __restrict__ outB,
                             int tt0, int* sidx) {
    const int tid = threadIdx.x;
    {
        int tk = tid >> 3, g = tid & 7;
        int tt = tt0 + tk, b = tt >> 12, t = tt & 4095;
        sidx[tk * 8 + g] = (int)outA[((size_t)(b * 8 + g)) * TLEN + t];
    }
    __syncthreads();

    const int tok = tid >> 3, vc = tid & 7;
    const int tt = tt0 + tok, b = tt >> 12, t = tt & 4095;
    const int h = vc >> 1, v0 = (vc & 1) * 32;

    float acc[32];
    const float* bp = head_b + h * 64 + v0;
#pragma unroll
    for (int j = 0; j < 8; j++) *(float4*)&acc[j * 4] = *(const float4*)&bp[j * 4];

#pragma unroll
    for (int g = 0; g < 8; g++) {
        const float* Lr = L + ((size_t)(g << 10) + sidx[tok * 8 + g]) * 256 + vc * 32;
#pragma unroll
        for (int j = 0; j < 8; j++) {
            float4 lv = *(const float4*)&Lr[j * 4];
            acc[j * 4] += lv.x; acc[j * 4 + 1] += lv.y;
            acc[j * 4 + 2] += lv.z; acc[j * 4 + 3] += lv.w;
        }
    }

    float* op = outB + (((size_t)(b * 4 + h)) * TLEN + t) * 64 + v0;
#pragma unroll
    for (int j = 0; j < 8; j++) *(float4*)&op[j * 4] = *(const float4*)&acc[j * 4];
}

// ================= persistent mega-kernel =================
__device__ __forceinline__ void wait_dep(int l, int b, int tbi, int need, int halo) {
    if (threadIdx.x == 0) {
        while (atomicAdd(&g_done[l][b][tbi], 0) < need) {}
        if (halo && tbi > 0)
            while (atomicAdd(&g_done[l][b][tbi - 1], 0) < need) {}
        __threadfence();
    }
    __syncthreads();
}

__global__ __launch_bounds__(256, 2)
void mega_kernel(const float* __restrict__ audio, const float* __restrict__ w1,
                 const float* __restrict__ b1,
                 const float* __restrict__ w2T, const float* __restrict__ b2,
                 const float* __restrict__ w3T, const float* __restrict__ b3,
                 const float* __restrict__ w4T, const float* __restrict__ b4,
                 const float* __restrict__ w5T, const float* __restrict__ b5,
                 const float* __restrict__ cbk, const float* __restrict__ cnm,
                 const float* __restrict__ Lt, const float* __restrict__ head_b,
                 float* __restrict__ x2, float* __restrict__ x3,
                 float* __restrict__ x4, float* __restrict__ x5,
                 float* __restrict__ out_a, float* __restrict__ outB,
                 float* __restrict__ part) {
    extern __shared__ float smem[];
    __shared__ int s_id;
    __shared__ int s_sidx[32 * 8];
    const int tid = threadIdx.x;

    for (;;) {
        if (tid == 0) s_id = atomicAdd(&g_qhead, 1);
        __syncthreads();
        const int id = s_id;
        if (id >= Q_END) return;

        int flag_l = -1, flag_b = 0, flag_tb = 0;

        if (id < Q_L1) {                      // conv12: (tb, b)
            int tbi = id >> 3, b = id & 7;
            tile_conv12(audio, w1, b1, w2T, b2, x2, b, tbi * 128, smem);
            flag_l = 0; flag_b = b; flag_tb = tbi;
        } else if (id < Q_L2) {               // conv3: (tb, b, cb of 2)
            int i2 = id - Q_L1;
            int tbi = i2 >> 4, b = (i2 >> 1) & 7, cbk_ = i2 & 1;
            wait_dep(0, b, tbi, 1, 1);
            tile_conv<128, 256, 5, 8, 1>(x2, w3T, b3, x3, b, tbi * 128, cbk_ * 128, smem);
            flag_l = 1; flag_b = b; flag_tb = tbi;
        } else if (id < Q_L3) {               // conv4: (tb, b, cb of 4)
            int i3 = id - Q_L2;
            int tbi = i3 >> 5, b = (i3 >> 2) & 7, cbk_ = i3 & 3;
            wait_dep(1, b, tbi, 2, 1);
            tile_conv<256, 512, 3, 16, 1>(x3, w4T, b4, x4, b, tbi * 128, cbk_ * 128, smem);
            flag_l = 2; flag_b = b; flag_tb = tbi;
        } else if (id < Q_L4) {               // conv5: (tb, b, cb of 4)
            int i4 = id - Q_L3;
            int tbi = i4 >> 5, b = (i4 >> 2) & 7, cbk_ = i4 & 3;
            wait_dep(2, b, tbi, 4, 1);
            tile_conv<512, 512, 3, 16, 0>(x4, w5T, b5, x5, b, tbi * 128, cbk_ * 128, smem);
            flag_l = 3; flag_b = b; flag_tb = tbi;
        } else if (id < Q_L5) {               // vq: (tb, b, g)
            int i5 = id - Q_L4;
            int tbi = i5 >> 6, b = (i5 >> 3) & 7, g = i5 & 7;
            wait_dep(3, b, tbi, 4, 0);
            tile_vq(x5, cbk, cnm, out_a, part, b, g, tbi, smem);
            flag_l = 4; flag_b = b; flag_tb = tbi;
        } else {                              // glogits: (tb, b, sub of 4)
            int i6 = id - Q_L5;
            int tbi = i6 >> 5, rem = i6 & 31, b = rem >> 2, sub = rem & 3;
            wait_dep(4, b, tbi, 8, 0);
            tile_glogits(out_a, Lt, head_b, outB, b * 4096 + tbi * 128 + sub * 32, s_sidx);
        }

        __syncthreads();
        if (tid == 0 && flag_l >= 0) {
            __threadfence();
            atomicAdd(&g_done[flag_l][flag_b][flag_tb], 1);
        }
    }
}

// ---------------- final loss ----------------
__global__ void loss_kernel(const float* __restrict__ partial, float* __restrict__ out) {
    __shared__ float s[256];
    int tid = threadIdx.x;
    float v = 0.f;
    for (int i = tid; i < 2048; i += 256) v += partial[i];
    s[tid] = v;
    __syncthreads();
    for (int k = 128; k > 0; k >>= 1) {
        if (tid < k) s[tid] += s[tid + k];
        __syncthreads();
    }
    if (tid == 0) out[0] = s[0] * (1.f / (8.f * 4096.f * 64.f));
}

// ---------------- launch ----------------
extern "C" void kernel_launch(void* const* d_in, const int* in_sizes, int n_in,
                              void* d_out, int out_size) {
    const float* audio = (const float*)d_in[0];
    const float* w1 = (const float*)d_in[1];
    const float* b1 = (const float*)d_in[2];
    const float* w2 = (const float*)d_in[3];
    const float* b2 = (const float*)d_in[4];
    const float* w3 = (const float*)d_in[5];
    const float* b3 = (const float*)d_in[6];
    const float* w4 = (const float*)d_in[7];
    const float* b4 = (const float*)d_in[8];
    const float* w5 = (const float*)d_in[9];
    const float* b5 = (const float*)d_in[10];
    const float* codebooks = (const float*)d_in[11];
    const float* head_w = (const float*)d_in[12];
    const float* head_b = (const float*)d_in[13];
    float* out = (float*)d_out;

    float *x2, *x3, *x4, *x5, *w2T, *w3T, *w4T, *w5T, *hwT, *cnm, *Lt, *part;
    cudaGetSymbolAddress((void**)&x2, g_x2);
    cudaGetSymbolAddress((void**)&x3, g_x3);
    cudaGetSymbolAddress((void**)&x4, g_x4);
    cudaGetSymbolAddress((void**)&x5, g_x5);
    cudaGetSymbolAddress((void**)&w2T, g_w2T);
    cudaGetSymbolAddress((void**)&w3T, g_w3T);
    cudaGetSymbolAddress((void**)&w4T, g_w4T);
    cudaGetSymbolAddress((void**)&w5T, g_w5T);
    cudaGetSymbolAddress((void**)&hwT, g_hwT);
    cudaGetSymbolAddress((void**)&cnm, g_cnorm);
    cudaGetSymbolAddress((void**)&Lt, g_L);
    cudaGetSymbolAddress((void**)&part, g_part);

    const int SM_CL = (2 * 64 * 132) * 4;

    cudaFuncSetAttribute((const void*)mega_kernel,
                         cudaFuncAttributeMaxDynamicSharedMemorySize, VQ_BYTES);
    cudaFuncSetAttribute((const void*)codelogits_kernel,
                         cudaFuncAttributeMaxDynamicSharedMemorySize, SM_CL);

    prep_kernel<<<(N_PREP + 255) / 256, 256>>>(w2, w3, w4, w5, head_w, codebooks,
                                               w2T, w3T, w4T, w5T, hwT, cnm);
    codelogits_kernel<<<dim3(8, 2, 8), 256, SM_CL>>>(codebooks, hwT, Lt);
    reset_kernel<<<6, 256>>>();

    mega_kernel<<<296, 256, VQ_BYTES>>>(audio, w1, b1, w2T, b2, w3T, b3,
                                        w4T, b4, w5T, b5, codebooks, cnm,
                                        Lt, head_b, x2, x3, x4, x5,
                                        out + OFF_A, out + OFF_B, part);

    loss_kernel<<<1, 256>>>(part, out + OFF_L);
}

// round 15
// speedup vs baseline: 1.0424x; 1.0424x over previous
#include <cuda_runtime.h>
#include <math.h>
#include <stdint.h>

// Problem constants
#define TLEN 4096
#define BSZ 8

typedef unsigned long long ull;

// Packed fp32x2 helpers
#define FMA2(acc, a, b) \
    asm("fma.rn.f32x2 %0, %1, %2, %3;" : "=l"(acc) : "l"(a), "l"(b), "l"(acc))
#define PACKB(d, s) \
    asm("mov.b64 %0, {%1, %1};" : "=l"(d) : "f"(s))
#define PACK2(d, lo, hi) \
    asm("mov.b64 %0, {%1, %2};" : "=l"(d) : "f"(lo), "f"(hi))
#define UNPACK2(lo, hi, s) \
    asm("mov.b64 {%0, %1}, %2;" : "=f"(lo), "=f"(hi) : "l"(s))

// cp.async primitives
__device__ __forceinline__ void cp4(uint32_t dst, const float* src, bool ok) {
    int sz = ok ? 4 : 0;
    asm volatile("cp.async.ca.shared.global [%0], [%1], 4, %2;"
                 :: "r"(dst), "l"(src), "r"(sz));
}
__device__ __forceinline__ void cp16(uint32_t dst, const void* src) {
    asm volatile("cp.async.cg.shared.global [%0], [%1], 16;"
                 :: "r"(dst), "l"(src));
}
#define CP_COMMIT() asm volatile("cp.async.commit_group;")
#define CP_WAIT(N) asm volatile("cp.async.wait_group %0;" :: "n"(N))

__device__ __forceinline__ int swz(int c) { return c ^ ((c >> 3) & 3); }
__device__ __forceinline__ int swzf(int p) { return (swz(p >> 2) << 2) | (p & 3); }

__device__ __forceinline__ uint32_t smem_u32(const void* p) {
    return (uint32_t)__cvta_generic_to_shared(p);
}

// ---------------- device scratch ----------------
__device__ float g_x2[BSZ * 128 * TLEN];
__device__ float g_x3[BSZ * 256 * TLEN];
__device__ float g_x4[BSZ * 512 * TLEN];
__device__ float g_x5[BSZ * 512 * TLEN];
__device__ float g_w2T[64 * 5 * 128];
__device__ float g_w3T[128 * 5 * 256];
__device__ float g_w4T[256 * 3 * 512];
__device__ float g_w5T[512 * 3 * 512];
__device__ float g_hwT[512 * 256];                 // head weights [d][h*64+v]
__device__ float g_cnorm[8 * 1024];
__device__ float g_cbkT[8 * 64 * 1024];            // codebook transposed [g][d][k]
__device__ float g_L[8 * 1024 * 256];              // code-logits table
__device__ float g_part[2048];

#define OFF_A 0
#define OFF_B (BSZ * 8 * TLEN)
#define OFF_L (OFF_B + BSZ * 4 * TLEN * 64)

// ---------------- prep (proven + codebook transpose) ----------------
__device__ __forceinline__ void tr_seg(int local, const float* __restrict__ w,
                                       float* __restrict__ wT, int CIN, int COUT, int K) {
    int co = local % COUT;
    int j = (local / COUT) % K;
    int ci = local / (COUT * K);
    wT[local] = w[((size_t)co * CIN + ci) * K + j];
}
#define N_W2 (64 * 5 * 128)
#define N_W3 (128 * 5 * 256)
#define N_W4 (256 * 3 * 512)
#define N_W5 (512 * 3 * 512)
#define N_HW (512 * 256)
#define N_CN (8 * 1024)
#define N_CBT (8 * 64 * 1024)
#define N_PREP (N_W2 + N_W3 + N_W4 + N_W5 + N_HW + N_CN + N_CBT)

__global__ void prep_kernel(const float* __restrict__ w2, const float* __restrict__ w3,
                            const float* __restrict__ w4, const float* __restrict__ w5,
                            const float* __restrict__ hw, const float* __restrict__ cbk,
                            float* __restrict__ w2T, float* __restrict__ w3T,
                            float* __restrict__ w4T, float* __restrict__ w5T,
                            float* __restrict__ hwT, float* __restrict__ cnorm,
                            float* __restrict__ cbkT) {
    int i = blockIdx.x * 256 + threadIdx.x;
    if (i < N_W2) { tr_seg(i, w2, w2T, 64, 128, 5); return; }
    i -= N_W2;
    if (i < N_W3) { tr_seg(i, w3, w3T, 128, 256, 5); return; }
    i -= N_W3;
    if (i < N_W4) { tr_seg(i, w4, w4T, 256, 512, 3); return; }
    i -= N_W4;
    if (i < N_W5) { tr_seg(i, w5, w5T, 512, 512, 3); return; }
    i -= N_W5;
    if (i < N_HW) {
        int co = i % 256, d = i / 256;
        int h = co >> 6, v = co & 63;
        hwT[i] = hw[((size_t)h * 512 + d) * 64 + v];
        return;
    }
    i -= N_HW;
    if (i < N_CN) {
        const float* row = cbk + (size_t)i * 64;
        float s = 0.f;
#pragma unroll 8
        for (int d = 0; d < 64; d++) { float v = row[d]; s += v * v; }
        cnorm[i] = s;
        return;
    }
    i -= N_CN;
    if (i < N_CBT) {
        int k = i & 1023, d = (i >> 10) & 63, g = i >> 16;
        cbkT[i] = cbk[(((size_t)g << 10) + k) * 64 + d];
    }
}

// ------- code-logits table (proven) -------
__global__ __launch_bounds__(256)
void codelogits_kernel(const float* __restrict__ cbk, const float* __restrict__ hwT,
                       float* __restrict__ L) {
    extern __shared__ float smc[];
    float* sct = smc;            // [64][132] codes transposed (d, k)
    float* sw = smc + 64 * 132;  // [64][132] weights (d, co)
    const int k0 = blockIdx.x * 128;
    const int co0 = blockIdx.y * 128;
    const int g = blockIdx.z;
    const int tid = threadIdx.x;
    const int tx = tid & 15, ty = tid >> 4;
    const int kb = tx * 8, cb = ty * 8;

    for (int i = tid; i < 8192; i += 256) {
        int k = i >> 6, d = i & 63;
        sct[d * 132 + k] = cbk[((size_t)g * 1024 + k0 + k) * 64 + d];
    }
    for (int i = tid; i < 8192; i += 256) {
        int d = i >> 7, co = i & 127;
        sw[d * 132 + co] = hwT[((size_t)(g * 64 + d)) * 256 + co0 + co];
    }
    __syncthreads();

    float acc[8][8];
#pragma unroll
    for (int a = 0; a < 8; a++)
#pragma unroll
        for (int c = 0; c < 8; c++) acc[a][c] = 0.f;

#pragma unroll 4
    for (int d = 0; d < 64; d++) {
        float kk[8], ww[8];
        *(float4*)&kk[0] = *(const float4*)&sct[d * 132 + kb];
        *(float4*)&kk[4] = *(const float4*)&sct[d * 132 + kb + 4];
        *(float4*)&ww[0] = *(const float4*)&sw[d * 132 + cb];
        *(float4*)&ww[4] = *(const float4*)&sw[d * 132 + cb + 4];
#pragma unroll
        for (int a = 0; a < 8; a++)
#pragma unroll
            for (int c = 0; c < 8; c++) acc[a][c] = fmaf(kk[a], ww[c], acc[a][c]);
    }

#pragma unroll
    for (int a = 0; a < 8; a++) {
        float* base = L + ((size_t)g * 1024 + k0 + kb + a) * 256 + co0 + cb;
        *(float4*)base = *(float4*)&acc[a][0];
        *(float4*)(base + 4) = *(float4*)&acc[a][4];
    }
}

// ------- logits gather (+ fused final loss in trailing block) ---------------
__global__ __launch_bounds__(256)
void glogits_kernel(const float* __restrict__ outA, const float* __restrict__ L,
                    const float* __restrict__ head_b, float* __restrict__ outB,
                    const float* __restrict__ partial, float* __restrict__ outLoss) {
    const int tid = threadIdx.x;

    if (blockIdx.x == 1024) {        // fused deterministic loss reduction
        __shared__ float s[256];
        float v = 0.f;
        for (int i = tid; i < 2048; i += 256) v += partial[i];
        s[tid] = v;
        __syncthreads();
        for (int k = 128; k > 0; k >>= 1) {
            if (tid < k) s[tid] += s[tid + k];
            __syncthreads();
        }
        if (tid == 0) outLoss[0] = s[0] * (1.f / (8.f * 4096.f * 64.f));
        return;
    }

    __shared__ int sidx[32][8];
    const int tt0 = blockIdx.x * 32;
    {
        int tk = tid >> 3, g = tid & 7;
        int tt = tt0 + tk, b = tt >> 12, t = tt & 4095;
        sidx[tk][g] = (int)outA[((size_t)(b * 8 + g)) * TLEN + t];
    }
    __syncthreads();

    const int tok = tid >> 3, vc = tid & 7;
    const int tt = tt0 + tok, b = tt >> 12, t = tt & 4095;
    const int h = vc >> 1, v0 = (vc & 1) * 32;

    float acc[32];
    const float* bp = head_b + h * 64 + v0;
#pragma unroll
    for (int j = 0; j < 8; j++) *(float4*)&acc[j * 4] = *(const float4*)&bp[j * 4];

#pragma unroll
    for (int g = 0; g < 8; g++) {
        const float* Lr = L + ((size_t)(g << 10) + sidx[tok][g]) * 256 + vc * 32;
#pragma unroll
        for (int j = 0; j < 8; j++) {
            float4 lv = *(const float4*)&Lr[j * 4];
            acc[j * 4] += lv.x; acc[j * 4 + 1] += lv.y;
            acc[j * 4 + 2] += lv.z; acc[j * 4 + 3] += lv.w;
        }
    }

    float* op = outB + (((size_t)(b * 4 + h)) * TLEN + t) * 64 + v0;
#pragma unroll
    for (int j = 0; j < 8; j++) *(float4*)&op[j * 4] = *(const float4*)&acc[j * 4];
}

// ------ conv1+conv2 fused (proven round 13, bitwise x1 math) ---------------
#define C12_XROW 136
#define C12_AUD 0
#define C12_W1 144
#define C12_B1 (144 + 448)
#define C12_X1 (144 + 448 + 64)
#define C12_WS (C12_X1 + 64 * C12_XROW)
#define C12_FLOATS (C12_WS + 3 * 5120)
#define C12_BYTES (C12_FLOATS * 4)

__global__ __launch_bounds__(256, 2)
void conv12_kernel(const float* __restrict__ audio, const float* __restrict__ w1,
                   const float* __restrict__ b1, const float* __restrict__ wT,
                   const float* __restrict__ bias, float* __restrict__ y) {
    constexpr int K = 5, COUT = 128, CI_CHUNK = 8;
    constexpr int NX = 12, NXF4 = 3;
    constexpr int WS_FL = CI_CHUNK * K * 128;
    constexpr int NCHUNK = 8;

    extern __shared__ float smem[];
    const uint32_t sb = smem_u32(smem);
    float* audio_s = smem + C12_AUD;
    float* w1s = smem + C12_W1;
    float* b1s = smem + C12_B1;
    float* x1s = smem + C12_X1;

    const int b = blockIdx.z, t0 = blockIdx.x * 128;
    const int tid = threadIdx.x;
    const int tx = tid & 15, ty = tid >> 4;
    const int tb = tx * 8, cb = ty * 8;

    auto loadW = [&](int c, int st) {
        uint32_t wbB = sb + (uint32_t)(C12_WS + st * WS_FL) * 4u;
        const int ci0 = c * CI_CHUNK;
        for (int i4 = tid * 4; i4 < WS_FL; i4 += 1024) {
            int cc = i4 / (K * 128);
            int rem = i4 % (K * 128);
            int j = rem / 128, co = rem % 128;
            cp16(wbB + (uint32_t)i4 * 4u,
                 wT + ((size_t)(ci0 + cc) * K + j) * COUT + co);
        }
        CP_COMMIT();
    };

    for (int i = tid; i < 138; i += 256) {
        int t = t0 - 10 + i;
        cp4(sb + (uint32_t)(C12_AUD + i) * 4u,
            audio + (size_t)b * TLEN + (t >= 0 ? t : 0), t >= 0);
    }
    for (int i4 = tid * 4; i4 < 448; i4 += 1024)
        cp16(sb + (uint32_t)(C12_W1 + i4) * 4u, w1 + i4);
    if (tid < 16)
        cp16(sb + (uint32_t)(C12_B1 + tid * 4) * 4u, b1 + tid * 4);
    CP_COMMIT();
    loadW(0, 0);
    loadW(1, 1);

    CP_WAIT(2);
    __syncthreads();

    for (int i = tid; i < 64 * 132; i += 256) {
        int ch = i / 132, p = i % 132;
        int t = t0 - 4 + p;
        float v = 0.f;
        if (t >= 0) {
            float acc = b1s[ch];
#pragma unroll
            for (int j = 0; j < 7; j++) acc += w1s[ch * 7 + j] * audio_s[p + j];
            v = acc > 0.f ? acc : expm1f(acc);
        }
        x1s[ch * C12_XROW + swzf(p)] = v;
    }
    __syncthreads();

    ull acc2[4][8];
#pragma unroll
    for (int rp = 0; rp < 4; rp++) {
        ull bb2;
        PACK2(bb2, bias[cb + 2 * rp], bias[cb + 2 * rp + 1]);
#pragma unroll
        for (int lt = 0; lt < 8; lt++) acc2[rp][lt] = bb2;
    }

    int st = 0;
#pragma unroll 1
    for (int c = 0; c < NCHUNK; c++) {
        if (c + 1 < NCHUNK) { CP_WAIT(1); } else { CP_WAIT(0); }
        __syncthreads();
        if (c + 2 < NCHUNK) {
            int st2 = st + 2; if (st2 >= 3) st2 -= 3;
            loadW(c + 2, st2);
        }
        const float* wsb = smem + C12_WS + st * WS_FL;
        const float* xbase = x1s + c * CI_CHUNK * C12_XROW;
#pragma unroll 1
        for (int cc = 0; cc < CI_CHUNK; cc++) {
            const float* xrow = xbase + cc * C12_XROW;
            float xv[NXF4 * 4];
#pragma unroll
            for (int q = 0; q < NXF4; q++)
                *(float4*)&xv[q * 4] = *(const float4*)&xrow[swz(tx * 2 + q) << 2];
            ull xb[NX];
#pragma unroll
            for (int p = 0; p < NX; p++) PACKB(xb[p], xv[p]);
#pragma unroll
            for (int j = 0; j < K; j++) {
                const float* wrow = wsb + (cc * K + j) * 128 + cb;
                ulonglong2 w01 = *(const ulonglong2*)&wrow[0];
                ulonglong2 w23 = *(const ulonglong2*)&wrow[4];
                ull wp[4] = {w01.x, w01.y, w23.x, w23.y};
#pragma unroll
                for (int rp = 0; rp < 4; rp++)
#pragma unroll
                    for (int lt = 0; lt < 8; lt++)
                        FMA2(acc2[rp][lt], wp[rp], xb[lt + j]);
            }
        }
        if (++st == 3) st = 0;
    }

    float accs[8][8];
#pragma unroll
    for (int rp = 0; rp < 4; rp++)
#pragma unroll
        for (int lt = 0; lt < 8; lt++)
            UNPACK2(accs[2 * rp][lt], accs[2 * rp + 1][lt], acc2[rp][lt]);

#pragma unroll
    for (int r = 0; r < 8; r++) {
        float o[8];
#pragma unroll
        for (int lt = 0; lt < 8; lt++) {
            float a = accs[r][lt];
            o[lt] = a > 0.f ? a : expm1f(a);
        }
        float* base = &y[((size_t)b * COUT + cb + r) * TLEN + t0 + tb];
        *(float4*)base = *(float4*)&o[0];
        *(float4*)(base + 4) = *(float4*)&o[4];
    }
}

// ---- conv-as-GEMM, proven (f32x2, 3-stage cp.async) — conv3/4/5 ----
template <int CIN, int COUT, int K, int CI_CHUNK, int ELU>
__global__ __launch_bounds__(256, 2)
void conv_gemm(const float* __restrict__ x, const float* __restrict__ wT,
               const float* __restrict__ bias, float* __restrict__ y) {
    constexpr int XROW = 136;
    constexpr int NX = 8 + K - 1;
    constexpr int NXF4 = (NX + 3) / 4;
    constexpr int XS_FL = CI_CHUNK * XROW;
    constexpr int WS_FL = CI_CHUNK * K * 128;
    constexpr int STG_FL = XS_FL + WS_FL;
    constexpr int NCHUNK = CIN / CI_CHUNK;

    extern __shared__ float smem[];
    const uint32_t sb = smem_u32(smem);
    const int b = blockIdx.z, t0 = blockIdx.x * 128, co0 = blockIdx.y * 128;
    const int tid = threadIdx.x;
    const int tx = tid & 15, ty = tid >> 4;
    const int tb = tx * 8, cb = ty * 8;

    auto load_chunk = [&](int c, int st) {
        const int ci0 = c * CI_CHUNK;
        uint32_t xbB = sb + (uint32_t)(st * STG_FL) * 4u;
        for (int i = tid; i < XS_FL; i += 256) {
            int cc = i / XROW, p = i % XROW;
            int t = t0 - (K - 1) + p;
            bool ok = (t >= 0) && (t < TLEN);
            const float* src = x + ((size_t)b * CIN + ci0 + cc) * TLEN + (ok ? t : 0);
            cp4(xbB + (uint32_t)(cc * XROW + swzf(p)) * 4u, src, ok);
        }
        uint32_t wbB = xbB + (uint32_t)XS_FL * 4u;
        for (int i4 = tid * 4; i4 < WS_FL; i4 += 1024) {
            int cc = i4 / (K * 128);
            int rem = i4 % (K * 128);
            int j = rem / 128, co = rem % 128;
            cp16(wbB + (uint32_t)i4 * 4u,
                 wT + ((size_t)(ci0 + cc) * K + j) * COUT + co0 + co);
        }
        CP_COMMIT();
    };

    load_chunk(0, 0);
    if (NCHUNK > 1) load_chunk(1, 1);

    ull acc2[4][8];
#pragma unroll
    for (int rp = 0; rp < 4; rp++) {
        ull bb2;
        PACK2(bb2, bias[co0 + cb + 2 * rp], bias[co0 + cb + 2 * rp + 1]);
#pragma unroll
        for (int lt = 0; lt < 8; lt++) acc2[rp][lt] = bb2;
    }

    int st = 0;
#pragma unroll 1
    for (int c = 0; c < NCHUNK; c++) {
        if (c + 1 < NCHUNK) { CP_WAIT(1); } else { CP_WAIT(0); }
        __syncthreads();
        if (c + 2 < NCHUNK) {
            int st2 = st + 2; if (st2 >= 3) st2 -= 3;
            load_chunk(c + 2, st2);
        }
        const float* xsb = smem + st * STG_FL;
        const float* wsb = xsb + XS_FL;
#pragma unroll 1
        for (int cc = 0; cc < CI_CHUNK; cc++) {
            const float* xrow = xsb + cc * XROW;
            float xv[NXF4 * 4];
#pragma unroll
            for (int q = 0; q < NXF4; q++)
                *(float4*)&xv[q * 4] = *(const float4*)&xrow[swz(tx * 2 + q) << 2];
            ull xb[NX];
#pragma unroll
            for (int p = 0; p < NX; p++) PACKB(xb[p], xv[p]);
#pragma unroll
            for (int j = 0; j < K; j++) {
                const float* wrow = wsb + (cc * K + j) * 128 + cb;
                ulonglong2 w01 = *(const ulonglong2*)&wrow[0];
                ulonglong2 w23 = *(const ulonglong2*)&wrow[4];
                ull wp[4] = {w01.x, w01.y, w23.x, w23.y};
#pragma unroll
                for (int rp = 0; rp < 4; rp++)
#pragma unroll
                    for (int lt = 0; lt < 8; lt++)
                        FMA2(acc2[rp][lt], wp[rp], xb[lt + j]);
            }
        }
        if (++st == 3) st = 0;
    }

    float accs[8][8];
#pragma unroll
    for (int rp = 0; rp < 4; rp++)
#pragma unroll
        for (int lt = 0; lt < 8; lt++)
            UNPACK2(accs[2 * rp][lt], accs[2 * rp + 1][lt], acc2[rp][lt]);

#pragma unroll
    for (int r = 0; r < 8; r++) {
        float o[8];
#pragma unroll
        for (int lt = 0; lt < 8; lt++) {
            float a = accs[r][lt];
            if (ELU) a = a > 0.f ? a : expm1f(a);
            o[lt] = a;
        }
        float* base = &y[((size_t)b * COUT + co0 + cb + r) * TLEN + t0 + tb];
        *(float4*)base = *(float4*)&o[0];
        *(float4*)(base + 4) = *(float4*)&o[4];
    }
}

// ---------------- VQ (proven math; cp16 loads from transposed inputs) -------
#define VQ_ZT 0
#define VQ_CB0 8192
#define VQ_CB1 (8192 + 8448)
#define VQ_CNORM (8192 + 16896)
#define VQ_ZN (VQ_CNORM + 1024)
#define VQ_BI (VQ_ZN + 128)
#define VQ_FLOATS (VQ_BI + 128)
#define VQ_BYTES (VQ_FLOATS * 4)
#define VQ_RV VQ_CB0
#define VQ_RI (VQ_CB0 + 2048)
#define VQ_LS VQ_CNORM

__global__ __launch_bounds__(256, 2)
void vq_kernel(const float* __restrict__ x5, const float* __restrict__ cbk,
               const float* __restrict__ cbkT, const float* __restrict__ cnormG,
               float* __restrict__ out_a, float* __restrict__ partial) {
    extern __shared__ float smem[];
    const uint32_t sb = smem_u32(smem);
    float* ztT = smem + VQ_ZT;
    float* cnormS = smem + VQ_CNORM;
    float* znorm = smem + VQ_ZN;
    int* besti = (int*)(smem + VQ_BI);
    float* redv = smem + VQ_RV;
    int* redi = (int*)(smem + VQ_RI);
    float* lscr = smem + VQ_LS;

    const int b = blockIdx.z, g = blockIdx.y;
    const int t0 = blockIdx.x * 128;
    const int tid = threadIdx.x;
    const int tx = tid & 15, ty = tid >> 4;
    const int trow = tx * 8, cbase = ty * 8;

    // z tile: cp16 (swzf is 16B-chunk-granular -> contiguous swizzled chunks)
    for (int i = tid; i < 2048; i += 256) {
        int d = i >> 5, ch = i & 31;
        cp16(sb + (uint32_t)(VQ_ZT + d * 128 + (swz(ch) << 2)) * 4u,
             x5 + (((size_t)b * 512) + (g << 6) + d) * TLEN + t0 + ch * 4);
    }
    cp16(sb + (uint32_t)(VQ_CNORM + tid * 4) * 4u, cnormG + g * 1024 + tid * 4);
    // codebook chunk 0: cp16 from pre-transposed cbkT (same smem layout as before)
    for (int i = tid; i < 2048; i += 256) {
        int d = i >> 5, u = i & 31;
        cp16(sb + (uint32_t)(VQ_CB0 + d * 132 + u * 4) * 4u,
             cbkT + (((size_t)g << 6) + d) * 1024 + u * 4);
    }
    CP_COMMIT();

    float zn[8], bv[8];
    int bi8[8];
#pragma unroll
    for (int a = 0; a < 8; a++) { bv[a] = 3.4e38f; bi8[a] = 0; }

#pragma unroll 1
    for (int c = 0; c < 8; c++) {
        const int k0 = c << 7;
        if (c + 1 < 8) {
            const int koff = (c + 1) << 7;
            uint32_t cbB = sb + (uint32_t)(((c + 1) & 1) ? VQ_CB1 : VQ_CB0) * 4u;
            for (int i = tid; i < 2048; i += 256) {
                int d = i >> 5, u = i & 31;
                cp16(cbB + (uint32_t)(d * 132 + u * 4) * 4u,
                     cbkT + (((size_t)g << 6) + d) * 1024 + koff + u * 4);
            }
            CP_COMMIT();
            CP_WAIT(1);
        } else {
            CP_WAIT(0);
        }
        __syncthreads();

        if (c == 0) {
            if (tid < 128) {
                float s = 0.f;
                int off = swzf(tid);
#pragma unroll 8
                for (int d = 0; d < 64; d++) { float v = ztT[d * 128 + off]; s += v * v; }
                znorm[tid] = s;
            }
            __syncthreads();
#pragma unroll
            for (int a = 0; a < 8; a++) zn[a] = znorm[trow + a];
        }

        const float* ct = smem + ((c & 1) ? VQ_CB1 : VQ_CB0);
        ull acc2[8][4];
#pragma unroll
        for (int a = 0; a < 8; a++)
#pragma unroll
            for (int q = 0; q < 4; q++) acc2[a][q] = 0ull;

#pragma unroll 4
        for (int d = 0; d < 64; d++) {
            float zz[8];
            *(float4*)&zz[0] = *(const float4*)&ztT[d * 128 + (swz(tx * 2) << 2)];
            *(float4*)&zz[4] = *(const float4*)&ztT[d * 128 + (swz(tx * 2 + 1) << 2)];
            ull zb[8];
#pragma unroll
            for (int a = 0; a < 8; a++) PACKB(zb[a], zz[a]);
            ulonglong2 c01 = *(const ulonglong2*)&ct[d * 132 + cbase];
            ulonglong2 c23 = *(const ulonglong2*)&ct[d * 132 + cbase + 4];
            ull cp_[4] = {c01.x, c01.y, c23.x, c23.y};
#pragma unroll
            for (int a = 0; a < 8; a++)
#pragma unroll
                for (int q = 0; q < 4; q++)
                    FMA2(acc2[a][q], zb[a], cp_[q]);
        }

        float accs[8][8];
#pragma unroll
        for (int a = 0; a < 8; a++)
#pragma unroll
            for (int q = 0; q < 4; q++)
                UNPACK2(accs[a][2 * q], accs[a][2 * q + 1], acc2[a][q]);

        float cn[8];
#pragma unroll
        for (int cc = 0; cc < 8; cc++) cn[cc] = cnormS[k0 + cbase + cc];
#pragma unroll
        for (int a = 0; a < 8; a++) {
#pragma unroll
            for (int cc = 0; cc < 8; cc++) {
                float dist = zn[a] + cn[cc] - 2.f * accs[a][cc];
                int idx = k0 + cbase + cc;
                if (dist < bv[a]) { bv[a] = dist; bi8[a] = idx; }
            }
        }
        __syncthreads();
    }

#pragma unroll
    for (int a = 0; a < 8; a++) {
        int tok = trow + a;
        redv[tok * 16 + ty] = bv[a];
        redi[tok * 16 + ty] = bi8[a];
    }
    __syncthreads();
    if (tid < 128) {
        float best = redv[tid * 16];
        int bidx = redi[tid * 16];
#pragma unroll
        for (int s = 1; s < 16; s++) {
            float v = redv[tid * 16 + s];
            int ii = redi[tid * 16 + s];
            if (v < best || (v == best && ii < bidx)) { best = v; bidx = ii; }
        }
        besti[tid] = bidx;
        out_a[((size_t)b * 8 + g) * TLEN + t0 + tid] = (float)bidx;
    }
    __syncthreads();

    float ls = 0.f;
    for (int i = tid; i < 64 * 128; i += 256) {
        int d = i & 63, lt = i >> 6;
        float qv = cbk[((size_t)g * 1024 + besti[lt]) * 64 + d];
        float df = qv - ztT[d * 128 + swzf(lt)];
        ls += df * df;
    }
    lscr[tid] = ls;
    __syncthreads();
    for (int s = 128; s > 0; s >>= 1) {
        if (tid < s) lscr[tid] += lscr[tid + s];
        __syncthreads();
    }
    if (tid == 0)
        partial[((size_t)b * 8 + g) * 32 + blockIdx.x] = lscr[0];
}

// ---------------- launch ----------------
extern "C" void kernel_launch(void* const* d_in, const int* in_sizes, int n_in,
                              void* d_out, int out_size) {
    const float* audio = (const float*)d_in[0];
    const float* w1 = (const float*)d_in[1];
    const float* b1 = (const float*)d_in[2];
    const float* w2 = (const float*)d_in[3];
    const float* b2 = (const float*)d_in[4];
    const float* w3 = (const float*)d_in[5];
    const float* b3 = (const float*)d_in[6];
    const float* w4 = (const float*)d_in[7];
    const float* b4 = (const float*)d_in[8];
    const float* w5 = (const float*)d_in[9];
    const float* b5 = (const float*)d_in[10];
    const float* codebooks = (const float*)d_in[11];
    const float* head_w = (const float*)d_in[12];
    const float* head_b = (const float*)d_in[13];
    float* out = (float*)d_out;

    float *x2, *x3, *x4, *x5, *w2T, *w3T, *w4T, *w5T, *hwT, *cnm, *cbT, *Lt, *part;
    cudaGetSymbolAddress((void**)&x2, g_x2);
    cudaGetSymbolAddress((void**)&x3, g_x3);
    cudaGetSymbolAddress((void**)&x4, g_x4);
    cudaGetSymbolAddress((void**)&x5, g_x5);
    cudaGetSymbolAddress((void**)&w2T, g_w2T);
    cudaGetSymbolAddress((void**)&w3T, g_w3T);
    cudaGetSymbolAddress((void**)&w4T, g_w4T);
    cudaGetSymbolAddress((void**)&w5T, g_w5T);
    cudaGetSymbolAddress((void**)&hwT, g_hwT);
    cudaGetSymbolAddress((void**)&cnm, g_cnorm);
    cudaGetSymbolAddress((void**)&cbT, g_cbkT);
    cudaGetSymbolAddress((void**)&Lt, g_L);
    cudaGetSymbolAddress((void**)&part, g_part);

    const int SM_C3 = (3 * (8 * 136 + 8 * 5 * 128)) * 4;
    const int SM_C4 = (3 * (16 * 136 + 16 * 3 * 128)) * 4;
    const int SM_C5 = SM_C4;
    const int SM_CL = (2 * 64 * 132) * 4;

    cudaFuncSetAttribute((const void*)conv12_kernel,
                         cudaFuncAttributeMaxDynamicSharedMemorySize, C12_BYTES);
    cudaFuncSetAttribute((const void*)conv_gemm<128, 256, 5, 8, 1>,
                         cudaFuncAttributeMaxDynamicSharedMemorySize, SM_C3);
    cudaFuncSetAttribute((const void*)conv_gemm<256, 512, 3, 16, 1>,
                         cudaFuncAttributeMaxDynamicSharedMemorySize, SM_C4);
    cudaFuncSetAttribute((const void*)conv_gemm<512, 512, 3, 16, 0>,
                         cudaFuncAttributeMaxDynamicSharedMemorySize, SM_C5);
    cudaFuncSetAttribute((const void*)codelogits_kernel,
                         cudaFuncAttributeMaxDynamicSharedMemorySize, SM_CL);
    cudaFuncSetAttribute((const void*)vq_kernel,
                         cudaFuncAttributeMaxDynamicSharedMemorySize, VQ_BYTES);

    prep_kernel<<<(N_PREP + 255) / 256, 256>>>(w2, w3, w4, w5, head_w, codebooks,
                                               w2T, w3T, w4T, w5T, hwT, cnm, cbT);
    codelogits_kernel<<<dim3(8, 2, 8), 256, SM_CL>>>(codebooks, hwT, Lt);

    conv12_kernel<<<dim3(32, 1, 8), 256, C12_BYTES>>>(audio, w1, b1, w2T, b2, x2);
    conv_gemm<128, 256, 5, 8, 1><<<dim3(32, 2, 8), 256, SM_C3>>>(x2, w3T, b3, x3);
    conv_gemm<256, 512, 3, 16, 1><<<dim3(32, 4, 8), 256, SM_C4>>>(x3, w4T, b4, x4);
    conv_gemm<512, 512, 3, 16, 0><<<dim3(32, 4, 8), 256, SM_C5>>>(x4, w5T, b5, x5);

    vq_kernel<<<dim3(32, 8, 8), 256, VQ_BYTES>>>(x5, codebooks, cbT, cnm,
                                                 out + OFF_A, part);
    glogits_kernel<<<1025, 256>>>(out + OFF_A, Lt, head_b, out + OFF_B,
                                  part, out + OFF_L);
}

// round 16
// speedup vs baseline: 1.0849x; 1.0408x over previous
#include <cuda_runtime.h>
#include <math.h>
#include <stdint.h>

// Problem constants
#define TLEN 4096
#define BSZ 8
#define TSP (TLEN + 4)          // padded row stride (data at [2, 2+TLEN))

typedef unsigned long long ull;

// Packed fp32x2 helpers
#define FMA2(acc, a, b) \
    asm("fma.rn.f32x2 %0, %1, %2, %3;" : "=l"(acc) : "l"(a), "l"(b), "l"(acc))
#define PACKB(d, s) \
    asm("mov.b64 %0, {%1, %1};" : "=l"(d) : "f"(s))
#define PACK2(d, lo, hi) \
    asm("mov.b64 %0, {%1, %2};" : "=l"(d) : "f"(lo), "f"(hi))
#define UNPACK2(lo, hi, s) \
    asm("mov.b64 {%0, %1}, %2;" : "=f"(lo), "=f"(hi) : "l"(s))

// cp.async primitives
__device__ __forceinline__ void cp4(uint32_t dst, const float* src, bool ok) {
    int sz = ok ? 4 : 0;
    asm volatile("cp.async.ca.shared.global [%0], [%1], 4, %2;"
                 :: "r"(dst), "l"(src), "r"(sz));
}
__device__ __forceinline__ void cp16(uint32_t dst, const void* src) {
    asm volatile("cp.async.cg.shared.global [%0], [%1], 16;"
                 :: "r"(dst), "l"(src));
}
__device__ __forceinline__ void cp16z(uint32_t dst, const void* src, bool ok) {
    int sz = ok ? 16 : 0;
    asm volatile("cp.async.cg.shared.global [%0], [%1], 16, %2;"
                 :: "r"(dst), "l"(src), "r"(sz));
}
#define CP_COMMIT() asm volatile("cp.async.commit_group;")
#define CP_WAIT(N) asm volatile("cp.async.wait_group %0;" :: "n"(N))

__device__ __forceinline__ int swz(int c) { return c ^ ((c >> 3) & 3); }
__device__ __forceinline__ int swzf(int p) { return (swz(p >> 2) << 2) | (p & 3); }

__device__ __forceinline__ uint32_t smem_u32(const void* p) {
    return (uint32_t)__cvta_generic_to_shared(p);
}

// ---------------- device scratch ----------------
__device__ float g_x2[BSZ * 128 * TLEN];
__device__ float g_x3p[BSZ * 256 * TSP];           // +2 padded rows
__device__ float g_x4p[BSZ * 512 * TSP];           // +2 padded rows
__device__ float g_x5[BSZ * 512 * TLEN];
__device__ float g_w2T[64 * 5 * 128];
__device__ float g_w3T[128 * 5 * 256];
__device__ float g_w4T[256 * 3 * 512];
__device__ float g_w5T[512 * 3 * 512];
__device__ float g_hwT[512 * 256];                 // head weights [d][h*64+v]
__device__ float g_cnorm[8 * 1024];
__device__ float g_cbkT[8 * 64 * 1024];            // codebook transposed [g][d][k]
__device__ float g_L[8 * 1024 * 256];              // code-logits table
__device__ float g_part[2048];

#define OFF_A 0
#define OFF_B (BSZ * 8 * TLEN)
#define OFF_L (OFF_B + BSZ * 4 * TLEN * 64)

// ---------------- prep (proven + codebook transpose + pad zeroing) ---------
__device__ __forceinline__ void tr_seg(int local, const float* __restrict__ w,
                                       float* __restrict__ wT, int CIN, int COUT, int K) {
    int co = local % COUT;
    int j = (local / COUT) % K;
    int ci = local / (COUT * K);
    wT[local] = w[((size_t)co * CIN + ci) * K + j];
}
#define N_W2 (64 * 5 * 128)
#define N_W3 (128 * 5 * 256)
#define N_W4 (256 * 3 * 512)
#define N_W5 (512 * 3 * 512)
#define N_HW (512 * 256)
#define N_CN (8 * 1024)
#define N_CBT (8 * 64 * 1024)
#define N_PX3 (BSZ * 256 * 4)
#define N_PX4 (BSZ * 512 * 4)
#define N_PREP (N_W2 + N_W3 + N_W4 + N_W5 + N_HW + N_CN + N_CBT + N_PX3 + N_PX4)

__global__ void prep_kernel(const float* __restrict__ w2, const float* __restrict__ w3,
                            const float* __restrict__ w4, const float* __restrict__ w5,
                            const float* __restrict__ hw, const float* __restrict__ cbk,
                            float* __restrict__ w2T, float* __restrict__ w3T,
                            float* __restrict__ w4T, float* __restrict__ w5T,
                            float* __restrict__ hwT, float* __restrict__ cnorm,
                            float* __restrict__ cbkT,
                            float* __restrict__ x3p, float* __restrict__ x4p) {
    int i = blockIdx.x * 256 + threadIdx.x;
    if (i < N_W2) { tr_seg(i, w2, w2T, 64, 128, 5); return; }
    i -= N_W2;
    if (i < N_W3) { tr_seg(i, w3, w3T, 128, 256, 5); return; }
    i -= N_W3;
    if (i < N_W4) { tr_seg(i, w4, w4T, 256, 512, 3); return; }
    i -= N_W4;
    if (i < N_W5) { tr_seg(i, w5, w5T, 512, 512, 3); return; }
    i -= N_W5;
    if (i < N_HW) {
        int co = i % 256, d = i / 256;
        int h = co >> 6, v = co & 63;
        hwT[i] = hw[((size_t)h * 512 + d) * 64 + v];
        return;
    }
    i -= N_HW;
    if (i < N_CN) {
        const float* row = cbk + (size_t)i * 64;
        float s = 0.f;
#pragma unroll 8
        for (int d = 0; d < 64; d++) { float v = row[d]; s += v * v; }
        cnorm[i] = s;
        return;
    }
    i -= N_CN;
    if (i < N_CBT) {
        int k = i & 1023, d = (i >> 10) & 63, g = i >> 16;
        cbkT[i] = cbk[(((size_t)g << 10) + k) * 64 + d];
        return;
    }
    i -= N_CBT;
    if (i < N_PX3) {
        int r = i >> 2, e = i & 3;
        x3p[(size_t)r * TSP + (e < 2 ? e : 4094 + e)] = 0.f;   // 0,1,4098,4099
        return;
    }
    i -= N_PX3;
    if (i < N_PX4) {
        int r = i >> 2, e = i & 3;
        x4p[(size_t)r * TSP + (e < 2 ? e : 4094 + e)] = 0.f;
    }
}

// ------- code-logits table (proven) -------
__global__ __launch_bounds__(256)
void codelogits_kernel(const float* __restrict__ cbk, const float* __restrict__ hwT,
                       float* __restrict__ L) {
    extern __shared__ float smc[];
    float* sct = smc;
    float* sw = smc + 64 * 132;
    const int k0 = blockIdx.x * 128;
    const int co0 = blockIdx.y * 128;
    const int g = blockIdx.z;
    const int tid = threadIdx.x;
    const int tx = tid & 15, ty = tid >> 4;
    const int kb = tx * 8, cb = ty * 8;

    for (int i = tid; i < 8192; i += 256) {
        int k = i >> 6, d = i & 63;
        sct[d * 132 + k] = cbk[((size_t)g * 1024 + k0 + k) * 64 + d];
    }
    for (int i = tid; i < 8192; i += 256) {
        int d = i >> 7, co = i & 127;
        sw[d * 132 + co] = hwT[((size_t)(g * 64 + d)) * 256 + co0 + co];
    }
    __syncthreads();

    float acc[8][8];
#pragma unroll
    for (int a = 0; a < 8; a++)
#pragma unroll
        for (int c = 0; c < 8; c++) acc[a][c] = 0.f;

#pragma unroll 4
    for (int d = 0; d < 64; d++) {
        float kk[8], ww[8];
        *(float4*)&kk[0] = *(const float4*)&sct[d * 132 + kb];
        *(float4*)&kk[4] = *(const float4*)&sct[d * 132 + kb + 4];
        *(float4*)&ww[0] = *(const float4*)&sw[d * 132 + cb];
        *(float4*)&ww[4] = *(const float4*)&sw[d * 132 + cb + 4];
#pragma unroll
        for (int a = 0; a < 8; a++)
#pragma unroll
            for (int c = 0; c < 8; c++) acc[a][c] = fmaf(kk[a], ww[c], acc[a][c]);
    }

#pragma unroll
    for (int a = 0; a < 8; a++) {
        float* base = L + ((size_t)g * 1024 + k0 + kb + a) * 256 + co0 + cb;
        *(float4*)base = *(float4*)&acc[a][0];
        *(float4*)(base + 4) = *(float4*)&acc[a][4];
    }
}

// ------- logits gather (+ fused final loss in trailing block) ---------------
__global__ __launch_bounds__(256)
void glogits_kernel(const float* __restrict__ outA, const float* __restrict__ L,
                    const float* __restrict__ head_b, float* __restrict__ outB,
                    const float* __restrict__ partial, float* __restrict__ outLoss) {
    const int tid = threadIdx.x;

    if (blockIdx.x == 1024) {
        __shared__ float s[256];
        float v = 0.f;
        for (int i = tid; i < 2048; i += 256) v += partial[i];
        s[tid] = v;
        __syncthreads();
        for (int k = 128; k > 0; k >>= 1) {
            if (tid < k) s[tid] += s[tid + k];
            __syncthreads();
        }
        if (tid == 0) outLoss[0] = s[0] * (1.f / (8.f * 4096.f * 64.f));
        return;
    }

    __shared__ int sidx[32][8];
    const int tt0 = blockIdx.x * 32;
    {
        int tk = tid >> 3, g = tid & 7;
        int tt = tt0 + tk, b = tt >> 12, t = tt & 4095;
        sidx[tk][g] = (int)outA[((size_t)(b * 8 + g)) * TLEN + t];
    }
    __syncthreads();

    const int tok = tid >> 3, vc = tid & 7;
    const int tt = tt0 + tok, b = tt >> 12, t = tt & 4095;
    const int h = vc >> 1, v0 = (vc & 1) * 32;

    float acc[32];
    const float* bp = head_b + h * 64 + v0;
#pragma unroll
    for (int j = 0; j < 8; j++) *(float4*)&acc[j * 4] = *(const float4*)&bp[j * 4];

#pragma unroll
    for (int g = 0; g < 8; g++) {
        const float* Lr = L + ((size_t)(g << 10) + sidx[tok][g]) * 256 + vc * 32;
#pragma unroll
        for (int j = 0; j < 8; j++) {
            float4 lv = *(const float4*)&Lr[j * 4];
            acc[j * 4] += lv.x; acc[j * 4 + 1] += lv.y;
            acc[j * 4 + 2] += lv.z; acc[j * 4 + 3] += lv.w;
        }
    }

    float* op = outB + (((size_t)(b * 4 + h)) * TLEN + t) * 64 + v0;
#pragma unroll
    for (int j = 0; j < 8; j++) *(float4*)&op[j * 4] = *(const float4*)&acc[j * 4];
}

// ------ conv1+conv2 fused (proven round 13, bitwise x1 math) ---------------
#define C12_XROW 136
#define C12_AUD 0
#define C12_W1 144
#define C12_B1 (144 + 448)
#define C12_X1 (144 + 448 + 64)
#define C12_WS (C12_X1 + 64 * C12_XROW)
#define C12_FLOATS (C12_WS + 3 * 5120)
#define C12_BYTES (C12_FLOATS * 4)

__global__ __launch_bounds__(256, 2)
void conv12_kernel(const float* __restrict__ audio, const float* __restrict__ w1,
                   const float* __restrict__ b1, const float* __restrict__ wT,
                   const float* __restrict__ bias, float* __restrict__ y) {
    constexpr int K = 5, COUT = 128, CI_CHUNK = 8;
    constexpr int NX = 12, NXF4 = 3;
    constexpr int WS_FL = CI_CHUNK * K * 128;
    constexpr int NCHUNK = 8;

    extern __shared__ float smem[];
    const uint32_t sb = smem_u32(smem);
    float* audio_s = smem + C12_AUD;
    float* w1s = smem + C12_W1;
    float* b1s = smem + C12_B1;
    float* x1s = smem + C12_X1;

    const int b = blockIdx.z, t0 = blockIdx.x * 128;
    const int tid = threadIdx.x;
    const int tx = tid & 15, ty = tid >> 4;
    const int tb = tx * 8, cb = ty * 8;

    auto loadW = [&](int c, int st) {
        uint32_t wbB = sb + (uint32_t)(C12_WS + st * WS_FL) * 4u;
        const int ci0 = c * CI_CHUNK;
        for (int i4 = tid * 4; i4 < WS_FL; i4 += 1024) {
            int cc = i4 / (K * 128);
            int rem = i4 % (K * 128);
            int j = rem / 128, co = rem % 128;
            cp16(wbB + (uint32_t)i4 * 4u,
                 wT + ((size_t)(ci0 + cc) * K + j) * COUT + co);
        }
        CP_COMMIT();
    };

    for (int i = tid; i < 138; i += 256) {
        int t = t0 - 10 + i;
        cp4(sb + (uint32_t)(C12_AUD + i) * 4u,
            audio + (size_t)b * TLEN + (t >= 0 ? t : 0), t >= 0);
    }
    for (int i4 = tid * 4; i4 < 448; i4 += 1024)
        cp16(sb + (uint32_t)(C12_W1 + i4) * 4u, w1 + i4);
    if (tid < 16)
        cp16(sb + (uint32_t)(C12_B1 + tid * 4) * 4u, b1 + tid * 4);
    CP_COMMIT();
    loadW(0, 0);
    loadW(1, 1);

    CP_WAIT(2);
    __syncthreads();

    for (int i = tid; i < 64 * 132; i += 256) {
        int ch = i / 132, p = i % 132;
        int t = t0 - 4 + p;
        float v = 0.f;
        if (t >= 0) {
            float acc = b1s[ch];
#pragma unroll
            for (int j = 0; j < 7; j++) acc += w1s[ch * 7 + j] * audio_s[p + j];
            v = acc > 0.f ? acc : expm1f(acc);
        }
        x1s[ch * C12_XROW + swzf(p)] = v;
    }
    __syncthreads();

    ull acc2[4][8];
#pragma unroll
    for (int rp = 0; rp < 4; rp++) {
        ull bb2;
        PACK2(bb2, bias[cb + 2 * rp], bias[cb + 2 * rp + 1]);
#pragma unroll
        for (int lt = 0; lt < 8; lt++) acc2[rp][lt] = bb2;
    }

    int st = 0;
#pragma unroll 1
    for (int c = 0; c < NCHUNK; c++) {
        if (c + 1 < NCHUNK) { CP_WAIT(1); } else { CP_WAIT(0); }
        __syncthreads();
        if (c + 2 < NCHUNK) {
            int st2 = st + 2; if (st2 >= 3) st2 -= 3;
            loadW(c + 2, st2);
        }
        const float* wsb = smem + C12_WS + st * WS_FL;
        const float* xbase = x1s + c * CI_CHUNK * C12_XROW;
#pragma unroll 1
        for (int cc = 0; cc < CI_CHUNK; cc++) {
            const float* xrow = xbase + cc * C12_XROW;
            float xv[NXF4 * 4];
#pragma unroll
            for (int q = 0; q < NXF4; q++)
                *(float4*)&xv[q * 4] = *(const float4*)&xrow[swz(tx * 2 + q) << 2];
            ull xb[NX];
#pragma unroll
            for (int p = 0; p < NX; p++) PACKB(xb[p], xv[p]);
#pragma unroll
            for (int j = 0; j < K; j++) {
                const float* wrow = wsb + (cc * K + j) * 128 + cb;
                ulonglong2 w01 = *(const ulonglong2*)&wrow[0];
                ulonglong2 w23 = *(const ulonglong2*)&wrow[4];
                ull wp[4] = {w01.x, w01.y, w23.x, w23.y};
#pragma unroll
                for (int rp = 0; rp < 4; rp++)
#pragma unroll
                    for (int lt = 0; lt < 8; lt++)
                        FMA2(acc2[rp][lt], wp[rp], xb[lt + j]);
            }
        }
        if (++st == 3) st = 0;
    }

    float accs[8][8];
#pragma unroll
    for (int rp = 0; rp < 4; rp++)
#pragma unroll
        for (int lt = 0; lt < 8; lt++)
            UNPACK2(accs[2 * rp][lt], accs[2 * rp + 1][lt], acc2[rp][lt]);

#pragma unroll
    for (int r = 0; r < 8; r++) {
        float o[8];
#pragma unroll
        for (int lt = 0; lt < 8; lt++) {
            float a = accs[r][lt];
            o[lt] = a > 0.f ? a : expm1f(a);
        }
        float* base = &y[((size_t)b * COUT + cb + r) * TLEN + t0 + tb];
        *(float4*)base = *(float4*)&o[0];
        *(float4*)(base + 4) = *(float4*)&o[4];
    }
}

// ---- conv-as-GEMM: f32x2, 3-stage cp.async, 16B x-loads ----
// IN_PAD: x rows have +2 pad (stride TSP) -> unconditional cp16 (K==3 only)
// !IN_PAD: requires K==5 (halo 4 -> 16B-aligned chunks) -> cp16z per chunk
// OUT_PAD: write to +2 padded rows via float2 stores
template <int CIN, int COUT, int K, int CI_CHUNK, int ELU, int IN_PAD, int OUT_PAD>
__global__ __launch_bounds__(256, 2)
void conv_gemm(const float* __restrict__ x, const float* __restrict__ wT,
               const float* __restrict__ bias, float* __restrict__ y) {
    constexpr int XROW = 136;
    constexpr int NX = 8 + K - 1;
    constexpr int NXF4 = (NX + 3) / 4;
    constexpr int XS_FL = CI_CHUNK * XROW;
    constexpr int WS_FL = CI_CHUNK * K * 128;
    constexpr int STG_FL = XS_FL + WS_FL;
    constexpr int NCHUNK = CIN / CI_CHUNK;
    constexpr int IN_TS = IN_PAD ? TSP : TLEN;
    constexpr int OUT_TS = OUT_PAD ? TSP : TLEN;
    constexpr int NQ = IN_PAD ? 33 : 34;       // 16B chunks per ci row

    extern __shared__ float smem[];
    const uint32_t sb = smem_u32(smem);
    const int b = blockIdx.z, t0 = blockIdx.x * 128, co0 = blockIdx.y * 128;
    const int tid = threadIdx.x;
    const int tx = tid & 15, ty = tid >> 4;
    const int tb = tx * 8, cb = ty * 8;

    auto load_chunk = [&](int c, int st) {
        const int ci0 = c * CI_CHUNK;
        uint32_t xbB = sb + (uint32_t)(st * STG_FL) * 4u;
        for (int i = tid; i < CI_CHUNK * NQ; i += 256) {
            int cc = i / NQ, q = i % NQ;
            uint32_t dst = xbB + (uint32_t)(cc * XROW + (swz(q) << 2)) * 4u;
            if (IN_PAD) {
                // addr = rowbase + 2 + (t0 - 2 + 4q) = rowbase + t0 + 4q (aligned)
                cp16(dst, x + (size_t)(b * CIN + ci0 + cc) * IN_TS + t0 + q * 4);
            } else {
                int t = t0 - (K - 1) + q * 4;   // K==5: 4-aligned, chunk all-in/out
                bool ok = (t >= 0) && (t < TLEN);
                cp16z(dst, x + (size_t)(b * CIN + ci0 + cc) * TLEN + (ok ? t : 0), ok);
            }
        }
        uint32_t wbB = xbB + (uint32_t)XS_FL * 4u;
        for (int i4 = tid * 4; i4 < WS_FL; i4 += 1024) {
            int cc = i4 / (K * 128);
            int rem = i4 % (K * 128);
            int j = rem / 128, co = rem % 128;
            cp16(wbB + (uint32_t)i4 * 4u,
                 wT + ((size_t)(ci0 + cc) * K + j) * COUT + co0 + co);
        }
        CP_COMMIT();
    };

    load_chunk(0, 0);
    if (NCHUNK > 1) load_chunk(1, 1);

    ull acc2[4][8];
#pragma unroll
    for (int rp = 0; rp < 4; rp++) {
        ull bb2;
        PACK2(bb2, bias[co0 + cb + 2 * rp], bias[co0 + cb + 2 * rp + 1]);
#pragma unroll
        for (int lt = 0; lt < 8; lt++) acc2[rp][lt] = bb2;
    }

    int st = 0;
#pragma unroll 1
    for (int c = 0; c < NCHUNK; c++) {
        if (c + 1 < NCHUNK) { CP_WAIT(1); } else { CP_WAIT(0); }
        __syncthreads();
        if (c + 2 < NCHUNK) {
            int st2 = st + 2; if (st2 >= 3) st2 -= 3;
            load_chunk(c + 2, st2);
        }
        const float* xsb = smem + st * STG_FL;
        const float* wsb = xsb + XS_FL;
#pragma unroll 1
        for (int cc = 0; cc < CI_CHUNK; cc++) {
            const float* xrow = xsb + cc * XROW;
            float xv[NXF4 * 4];
#pragma unroll
            for (int q = 0; q < NXF4; q++)
                *(float4*)&xv[q * 4] = *(const float4*)&xrow[swz(tx * 2 + q) << 2];
            ull xb[NX];
#pragma unroll
            for (int p = 0; p < NX; p++) PACKB(xb[p], xv[p]);
#pragma unroll
            for (int j = 0; j < K; j++) {
                const float* wrow = wsb + (cc * K + j) * 128 + cb;
                ulonglong2 w01 = *(const ulonglong2*)&wrow[0];
                ulonglong2 w23 = *(const ulonglong2*)&wrow[4];
                ull wp[4] = {w01.x, w01.y, w23.x, w23.y};
#pragma unroll
                for (int rp = 0; rp < 4; rp++)
#pragma unroll
                    for (int lt = 0; lt < 8; lt++)
                        FMA2(acc2[rp][lt], wp[rp], xb[lt + j]);
            }
        }
        if (++st == 3) st = 0;
    }

    float accs[8][8];
#pragma unroll
    for (int rp = 0; rp < 4; rp++)
#pragma unroll
        for (int lt = 0; lt < 8; lt++)
            UNPACK2(accs[2 * rp][lt], accs[2 * rp + 1][lt], acc2[rp][lt]);

#pragma unroll
    for (int r = 0; r < 8; r++) {
        float o[8];
#pragma unroll
        for (int lt = 0; lt < 8; lt++) {
            float a = accs[r][lt];
            if (ELU) a = a > 0.f ? a : expm1f(a);
            o[lt] = a;
        }
        if (OUT_PAD) {
            float* base = &y[(size_t)(b * COUT + co0 + cb + r) * OUT_TS + 2 + t0 + tb];
#pragma unroll
            for (int h = 0; h < 4; h++)
                *(float2*)(base + 2 * h) = make_float2(o[2 * h], o[2 * h + 1]);
        } else {
            float* base = &y[(size_t)(b * COUT + co0 + cb + r) * OUT_TS + t0 + tb];
            *(float4*)base = *(float4*)&o[0];
            *(float4*)(base + 4) = *(float4*)&o[4];
        }
    }
}

// ---------------- VQ (proven round-15: cp16 transposed loads) --------------
#define VQ_ZT 0
#define VQ_CB0 8192
#define VQ_CB1 (8192 + 8448)
#define VQ_CNORM (8192 + 16896)
#define VQ_ZN (VQ_CNORM + 1024)
#define VQ_BI (VQ_ZN + 128)
#define VQ_FLOATS (VQ_BI + 128)
#define VQ_BYTES (VQ_FLOATS * 4)
#define VQ_RV VQ_CB0
#define VQ_RI (VQ_CB0 + 2048)
#define VQ_LS VQ_CNORM

__global__ __launch_bounds__(256, 2)
void vq_kernel(const float* __restrict__ x5, const float* __restrict__ cbk,
               const float* __restrict__ cbkT, const float* __restrict__ cnormG,
               float* __restrict__ out_a, float* __restrict__ partial) {
    extern __shared__ float smem[];
    const uint32_t sb = smem_u32(smem);
    float* ztT = smem + VQ_ZT;
    float* cnormS = smem + VQ_CNORM;
    float* znorm = smem + VQ_ZN;
    int* besti = (int*)(smem + VQ_BI);
    float* redv = smem + VQ_RV;
    int* redi = (int*)(smem + VQ_RI);
    float* lscr = smem + VQ_LS;

    const int b = blockIdx.z, g = blockIdx.y;
    const int t0 = blockIdx.x * 128;
    const int tid = threadIdx.x;
    const int tx = tid & 15, ty = tid >> 4;
    const int trow = tx * 8, cbase = ty * 8;

    for (int i = tid; i < 2048; i += 256) {
        int d = i >> 5, ch = i & 31;
        cp16(sb + (uint32_t)(VQ_ZT + d * 128 + (swz(ch) << 2)) * 4u,
             x5 + (((size_t)b * 512) + (g << 6) + d) * TLEN + t0 + ch * 4);
    }
    cp16(sb + (uint32_t)(VQ_CNORM + tid * 4) * 4u, cnormG + g * 1024 + tid * 4);
    for (int i = tid; i < 2048; i += 256) {
        int d = i >> 5, u = i & 31;
        cp16(sb + (uint32_t)(VQ_CB0 + d * 132 + u * 4) * 4u,
             cbkT + (((size_t)g << 6) + d) * 1024 + u * 4);
    }
    CP_COMMIT();

    float zn[8], bv[8];
    int bi8[8];
#pragma unroll
    for (int a = 0; a < 8; a++) { bv[a] = 3.4e38f; bi8[a] = 0; }

#pragma unroll 1
    for (int c = 0; c < 8; c++) {
        const int k0 = c << 7;
        if (c + 1 < 8) {
            const int koff = (c + 1) << 7;
            uint32_t cbB = sb + (uint32_t)(((c + 1) & 1) ? VQ_CB1 : VQ_CB0) * 4u;
            for (int i = tid; i < 2048; i += 256) {
                int d = i >> 5, u = i & 31;
                cp16(cbB + (uint32_t)(d * 132 + u * 4) * 4u,
                     cbkT + (((size_t)g << 6) + d) * 1024 + koff + u * 4);
            }
            CP_COMMIT();
            CP_WAIT(1);
        } else {
            CP_WAIT(0);
        }
        __syncthreads();

        if (c == 0) {
            if (tid < 128) {
                float s = 0.f;
                int off = swzf(tid);
#pragma unroll 8
                for (int d = 0; d < 64; d++) { float v = ztT[d * 128 + off]; s += v * v; }
                znorm[tid] = s;
            }
            __syncthreads();
#pragma unroll
            for (int a = 0; a < 8; a++) zn[a] = znorm[trow + a];
        }

        const float* ct = smem + ((c & 1) ? VQ_CB1 : VQ_CB0);
        ull acc2[8][4];
#pragma unroll
        for (int a = 0; a < 8; a++)
#pragma unroll
            for (int q = 0; q < 4; q++) acc2[a][q] = 0ull;

#pragma unroll 4
        for (int d = 0; d < 64; d++) {
            float zz[8];
            *(float4*)&zz[0] = *(const float4*)&ztT[d * 128 + (swz(tx * 2) << 2)];
            *(float4*)&zz[4] = *(const float4*)&ztT[d * 128 + (swz(tx * 2 + 1) << 2)];
            ull zb[8];
#pragma unroll
            for (int a = 0; a < 8; a++) PACKB(zb[a], zz[a]);
            ulonglong2 c01 = *(const ulonglong2*)&ct[d * 132 + cbase];
            ulonglong2 c23 = *(const ulonglong2*)&ct[d * 132 + cbase + 4];
            ull cp_[4] = {c01.x, c01.y, c23.x, c23.y};
#pragma unroll
            for (int a = 0; a < 8; a++)
#pragma unroll
                for (int q = 0; q < 4; q++)
                    FMA2(acc2[a][q], zb[a], cp_[q]);
        }

        float accs[8][8];
#pragma unroll
        for (int a = 0; a < 8; a++)
#pragma unroll
            for (int q = 0; q < 4; q++)
                UNPACK2(accs[a][2 * q], accs[a][2 * q + 1], acc2[a][q]);

        float cn[8];
#pragma unroll
        for (int cc = 0; cc < 8; cc++) cn[cc] = cnormS[k0 + cbase + cc];
#pragma unroll
        for (int a = 0; a < 8; a++) {
#pragma unroll
            for (int cc = 0; cc < 8; cc++) {
                float dist = zn[a] + cn[cc] - 2.f * accs[a][cc];
                int idx = k0 + cbase + cc;
                if (dist < bv[a]) { bv[a] = dist; bi8[a] = idx; }
            }
        }
        __syncthreads();
    }

#pragma unroll
    for (int a = 0; a < 8; a++) {
        int tok = trow + a;
        redv[tok * 16 + ty] = bv[a];
        redi[tok * 16 + ty] = bi8[a];
    }
    __syncthreads();
    if (tid < 128) {
        float best = redv[tid * 16];
        int bidx = redi[tid * 16];
#pragma unroll
        for (int s = 1; s < 16; s++) {
            float v = redv[tid * 16 + s];
            int ii = redi[tid * 16 + s];
            if (v < best || (v == best && ii < bidx)) { best = v; bidx = ii; }
        }
        besti[tid] = bidx;
        out_a[((size_t)b * 8 + g) * TLEN + t0 + tid] = (float)bidx;
    }
    __syncthreads();

    float ls = 0.f;
    for (int i = tid; i < 64 * 128; i += 256) {
        int d = i & 63, lt = i >> 6;
        float qv = cbk[((size_t)g * 1024 + besti[lt]) * 64 + d];
        float df = qv - ztT[d * 128 + swzf(lt)];
        ls += df * df;
    }
    lscr[tid] = ls;
    __syncthreads();
    for (int s = 128; s > 0; s >>= 1) {
        if (tid < s) lscr[tid] += lscr[tid + s];
        __syncthreads();
    }
    if (tid == 0)
        partial[((size_t)b * 8 + g) * 32 + blockIdx.x] = lscr[0];
}

// ---------------- launch ----------------
extern "C" void kernel_launch(void* const* d_in, const int* in_sizes, int n_in,
                              void* d_out, int out_size) {
    const float* audio = (const float*)d_in[0];
    const float* w1 = (const float*)d_in[1];
    const float* b1 = (const float*)d_in[2];
    const float* w2 = (const float*)d_in[3];
    const float* b2 = (const float*)d_in[4];
    const float* w3 = (const float*)d_in[5];
    const float* b3 = (const float*)d_in[6];
    const float* w4 = (const float*)d_in[7];
    const float* b4 = (const float*)d_in[8];
    const float* w5 = (const float*)d_in[9];
    const float* b5 = (const float*)d_in[10];
    const float* codebooks = (const float*)d_in[11];
    const float* head_w = (const float*)d_in[12];
    const float* head_b = (const float*)d_in[13];
    float* out = (float*)d_out;

    float *x2, *x3p, *x4p, *x5, *w2T, *w3T, *w4T, *w5T, *hwT, *cnm, *cbT, *Lt, *part;
    cudaGetSymbolAddress((void**)&x2, g_x2);
    cudaGetSymbolAddress((void**)&x3p, g_x3p);
    cudaGetSymbolAddress((void**)&x4p, g_x4p);
    cudaGetSymbolAddress((void**)&x5, g_x5);
    cudaGetSymbolAddress((void**)&w2T, g_w2T);
    cudaGetSymbolAddress((void**)&w3T, g_w3T);
    cudaGetSymbolAddress((void**)&w4T, g_w4T);
    cudaGetSymbolAddress((void**)&w5T, g_w5T);
    cudaGetSymbolAddress((void**)&hwT, g_hwT);
    cudaGetSymbolAddress((void**)&cnm, g_cnorm);
    cudaGetSymbolAddress((void**)&cbT, g_cbkT);
    cudaGetSymbolAddress((void**)&Lt, g_L);
    cudaGetSymbolAddress((void**)&part, g_part);

    const int SM_C3 = (3 * (8 * 136 + 8 * 5 * 128)) * 4;
    const int SM_C4 = (3 * (16 * 136 + 16 * 3 * 128)) * 4;
    const int SM_C5 = SM_C4;
    const int SM_CL = (2 * 64 * 132) * 4;

    cudaFuncSetAttribute((const void*)conv12_kernel,
                         cudaFuncAttributeMaxDynamicSharedMemorySize, C12_BYTES);
    cudaFuncSetAttribute((const void*)conv_gemm<128, 256, 5, 8, 1, 0, 1>,
                         cudaFuncAttributeMaxDynamicSharedMemorySize, SM_C3);
    cudaFuncSetAttribute((const void*)conv_gemm<256, 512, 3, 16, 1, 1, 1>,
                         cudaFuncAttributeMaxDynamicSharedMemorySize, SM_C4);
    cudaFuncSetAttribute((const void*)conv_gemm<512, 512, 3, 16, 0, 1, 0>,
                         cudaFuncAttributeMaxDynamicSharedMemorySize, SM_C5);
    cudaFuncSetAttribute((const void*)codelogits_kernel,
                         cudaFuncAttributeMaxDynamicSharedMemorySize, SM_CL);
    cudaFuncSetAttribute((const void*)vq_kernel,
                         cudaFuncAttributeMaxDynamicSharedMemorySize, VQ_BYTES);

    prep_kernel<<<(N_PREP + 255) / 256, 256>>>(w2, w3, w4, w5, head_w, codebooks,
                                               w2T, w3T, w4T, w5T, hwT, cnm, cbT,
                                               x3p, x4p);
    codelogits_kernel<<<dim3(8, 2, 8), 256, SM_CL>>>(codebooks, hwT, Lt);

    conv12_kernel<<<dim3(32, 1, 8), 256, C12_BYTES>>>(audio, w1, b1, w2T, b2, x2);
    conv_gemm<128, 256, 5, 8, 1, 0, 1><<<dim3(32, 2, 8), 256, SM_C3>>>(x2, w3T, b3, x3p);
    conv_gemm<256, 512, 3, 16, 1, 1, 1><<<dim3(32, 4, 8), 256, SM_C4>>>(x3p, w4T, b4, x4p);
    conv_gemm<512, 512, 3, 16, 0, 1, 0><<<dim3(32, 4, 8), 256, SM_C5>>>(x4p, w5T, b5, x5);

    vq_kernel<<<dim3(32, 8, 8), 256, VQ_BYTES>>>(x5, codebooks, cbT, cnm,
                                                 out + OFF_A, part);
    glogits_kernel<<<1025, 256>>>(out + OFF_A, Lt, head_b, out + OFF_B,
                                  part, out + OFF_L);
}

// round 17
// speedup vs baseline: 1.1991x; 1.1052x over previous
#include <cuda_runtime.h>
#include <math.h>
#include <stdint.h>

// Problem constants
#define TLEN 4096
#define BSZ 8
#define TSP (TLEN + 4)          // padded row stride (data at [2, 2+TLEN))

typedef unsigned long long ull;

// Packed fp32x2 helpers
#define FMA2(acc, a, b) \
    asm("fma.rn.f32x2 %0, %1, %2, %3;" : "=l"(acc) : "l"(a), "l"(b), "l"(acc))
#define PACKB(d, s) \
    asm("mov.b64 %0, {%1, %1};" : "=l"(d) : "f"(s))
#define PACK2(d, lo, hi) \
    asm("mov.b64 %0, {%1, %2};" : "=l"(d) : "f"(lo), "f"(hi))
#define UNPACK2(lo, hi, s) \
    asm("mov.b64 {%0, %1}, %2;" : "=f"(lo), "=f"(hi) : "l"(s))

// cp.async primitives
__device__ __forceinline__ void cp4(uint32_t dst, const float* src, bool ok) {
    int sz = ok ? 4 : 0;
    asm volatile("cp.async.ca.shared.global [%0], [%1], 4, %2;"
                 :: "r"(dst), "l"(src), "r"(sz));
}
__device__ __forceinline__ void cp16(uint32_t dst, const void* src) {
    asm volatile("cp.async.cg.shared.global [%0], [%1], 16;"
                 :: "r"(dst), "l"(src));
}
__device__ __forceinline__ void cp16z(uint32_t dst, const void* src, bool ok) {
    int sz = ok ? 16 : 0;
    asm volatile("cp.async.cg.shared.global [%0], [%1], 16, %2;"
                 :: "r"(dst), "l"(src), "r"(sz));
}
#define CP_COMMIT() asm volatile("cp.async.commit_group;")
#define CP_WAIT(N) asm volatile("cp.async.wait_group %0;" :: "n"(N))

__device__ __forceinline__ int swz(int c) { return c ^ ((c >> 3) & 3); }
__device__ __forceinline__ int swzf(int p) { return (swz(p >> 2) << 2) | (p & 3); }

__device__ __forceinline__ uint32_t smem_u32(const void* p) {
    return (uint32_t)__cvta_generic_to_shared(p);
}

// order-preserving float<->uint encoding for smem atomicMin
__device__ __forceinline__ unsigned encf(float f) {
    unsigned b = __float_as_uint(f);
    return (b & 0x80000000u) ? ~b : (b | 0x80000000u);
}
__device__ __forceinline__ float decf(unsigned u) {
    return __uint_as_float((u & 0x80000000u) ? (u & 0x7FFFFFFFu) : ~u);
}

// ---------------- device scratch ----------------
__device__ float g_x2[BSZ * 128 * TLEN];
__device__ float g_x3p[BSZ * 256 * TSP];           // +2 padded rows
__device__ float g_x4p[BSZ * 512 * TSP];           // +2 padded rows
__device__ float g_x5[BSZ * 512 * TLEN];
__device__ float g_w2T[64 * 5 * 128];
__device__ float g_w3T[128 * 5 * 256];
__device__ float g_w4T[256 * 3 * 512];
__device__ float g_w5T[512 * 3 * 512];
__device__ float g_hwT[512 * 256];                 // head weights [d][h*64+v]
__device__ float g_cnorm[8 * 1024];
__device__ int   g_cb8[8 * 8 * 16 * 128];          // int8-packed codes [g][ch][dq][k]
__device__ float g_csc[8 * 1024];                  // per-code scale
__device__ float g_cA[8 * 1024];                   // per-code sc*(L1+32)
__device__ float g_gstat[8 * 4];                   // per-group {Amax, scmax, cnmax}
__device__ float g_L[8 * 1024 * 256];              // code-logits table
__device__ float g_part[2048];

#define OFF_A 0
#define OFF_B (BSZ * 8 * TLEN)
#define OFF_L (OFF_B + BSZ * 4 * TLEN * 64)

// ---------------- prep ----------------
__device__ __forceinline__ void tr_seg(int local, const float* __restrict__ w,
                                       float* __restrict__ wT, int CIN, int COUT, int K) {
    int co = local % COUT;
    int j = (local / COUT) % K;
    int ci = local / (COUT * K);
    wT[local] = w[((size_t)co * CIN + ci) * K + j];
}
#define N_W2 (64 * 5 * 128)
#define N_W3 (128 * 5 * 256)
#define N_W4 (256 * 3 * 512)
#define N_W5 (512 * 3 * 512)
#define N_HW (512 * 256)
#define N_CN (8 * 1024)
#define N_CQ (8 * 1024)
#define N_PX3 (BSZ * 256 * 4)
#define N_PX4 (BSZ * 512 * 4)
#define N_PREP (N_W2 + N_W3 + N_W4 + N_W5 + N_HW + N_CN + N_CQ + N_PX3 + N_PX4)

__global__ void prep_kernel(const float* __restrict__ w2, const float* __restrict__ w3,
                            const float* __restrict__ w4, const float* __restrict__ w5,
                            const float* __restrict__ hw, const float* __restrict__ cbk,
                            float* __restrict__ w2T, float* __restrict__ w3T,
                            float* __restrict__ w4T, float* __restrict__ w5T,
                            float* __restrict__ hwT, float* __restrict__ cnorm,
                            float* __restrict__ x3p, float* __restrict__ x4p) {
    int i = blockIdx.x * 256 + threadIdx.x;
    if (i < N_W2) { tr_seg(i, w2, w2T, 64, 128, 5); return; }
    i -= N_W2;
    if (i < N_W3) { tr_seg(i, w3, w3T, 128, 256, 5); return; }
    i -= N_W3;
    if (i < N_W4) { tr_seg(i, w4, w4T, 256, 512, 3); return; }
    i -= N_W4;
    if (i < N_W5) { tr_seg(i, w5, w5T, 512, 512, 3); return; }
    i -= N_W5;
    if (i < N_HW) {
        int co = i % 256, d = i / 256;
        int h = co >> 6, v = co & 63;
        hwT[i] = hw[((size_t)h * 512 + d) * 64 + v];
        return;
    }
    i -= N_HW;
    if (i < N_CN) {
        const float* row = cbk + (size_t)i * 64;
        float s = 0.f;
#pragma unroll 8
        for (int d = 0; d < 64; d++) { float v = row[d]; s += v * v; }
        cnorm[i] = s;
        return;
    }
    i -= N_CN;
    if (i < N_CQ) {
        // int8 quantization of code i (g = i>>10, kl = i&1023)
        const float* row = cbk + (size_t)i * 64;
        int g = i >> 10, kl = i & 1023;
        float M = 0.f;
#pragma unroll 8
        for (int d = 0; d < 64; d++) M = fmaxf(M, fabsf(row[d]));
        float Msafe = fmaxf(M, 1e-30f);
        float sc = Msafe / 127.f;
        float inv = 127.f / Msafe;
        int L1 = 0;
#pragma unroll
        for (int dq = 0; dq < 16; dq++) {
            int p = 0;
#pragma unroll
            for (int j = 0; j < 4; j++) {
                int q = __float2int_rn(row[dq * 4 + j] * inv);
                q = q > 127 ? 127 : (q < -127 ? -127 : q);
                L1 += (q < 0 ? -q : q);
                p |= (q & 0xFF) << (8 * j);
            }
            g_cb8[(((g * 8 + (kl >> 7)) * 16 + dq) << 7) + (kl & 127)] = p;
        }
        g_csc[i] = sc;
        g_cA[i] = sc * (float)(L1 + 32);
        return;
    }
    i -= N_CQ;
    if (i < N_PX3) {
        int r = i >> 2, e = i & 3;
        x3p[(size_t)r * TSP + (e < 2 ? e : 4094 + e)] = 0.f;
        return;
    }
    i -= N_PX3;
    if (i < N_PX4) {
        int r = i >> 2, e = i & 3;
        x4p[(size_t)r * TSP + (e < 2 ? e : 4094 + e)] = 0.f;
    }
}

// ------- per-group stats: Amax, scmax, cnmax -------
__global__ void gstat_kernel(const float* __restrict__ cA, const float* __restrict__ csc,
                             const float* __restrict__ cnorm, float* __restrict__ gs) {
    __shared__ float sA[256], sS[256], sN[256];
    const int g = blockIdx.x, tid = threadIdx.x;
    float a = 0.f, s = 0.f, n = 0.f;
    for (int i = tid; i < 1024; i += 256) {
        a = fmaxf(a, cA[g * 1024 + i]);
        s = fmaxf(s, csc[g * 1024 + i]);
        n = fmaxf(n, cnorm[g * 1024 + i]);
    }
    sA[tid] = a; sS[tid] = s; sN[tid] = n;
    __syncthreads();
    for (int k = 128; k > 0; k >>= 1) {
        if (tid < k) {
            sA[tid] = fmaxf(sA[tid], sA[tid + k]);
            sS[tid] = fmaxf(sS[tid], sS[tid + k]);
            sN[tid] = fmaxf(sN[tid], sN[tid + k]);
        }
        __syncthreads();
    }
    if (tid == 0) { gs[g * 4] = sA[0]; gs[g * 4 + 1] = sS[0]; gs[g * 4 + 2] = sN[0]; }
}

// ------- code-logits table (proven) -------
__global__ __launch_bounds__(256)
void codelogits_kernel(const float* __restrict__ cbk, const float* __restrict__ hwT,
                       float* __restrict__ L) {
    extern __shared__ float smc[];
    float* sct = smc;
    float* sw = smc + 64 * 132;
    const int k0 = blockIdx.x * 128;
    const int co0 = blockIdx.y * 128;
    const int g = blockIdx.z;
    const int tid = threadIdx.x;
    const int tx = tid & 15, ty = tid >> 4;
    const int kb = tx * 8, cb = ty * 8;

    for (int i = tid; i < 8192; i += 256) {
        int k = i >> 6, d = i & 63;
        sct[d * 132 + k] = cbk[((size_t)g * 1024 + k0 + k) * 64 + d];
    }
    for (int i = tid; i < 8192; i += 256) {
        int d = i >> 7, co = i & 127;
        sw[d * 132 + co] = hwT[((size_t)(g * 64 + d)) * 256 + co0 + co];
    }
    __syncthreads();

    float acc[8][8];
#pragma unroll
    for (int a = 0; a < 8; a++)
#pragma unroll
        for (int c = 0; c < 8; c++) acc[a][c] = 0.f;

#pragma unroll 4
    for (int d = 0; d < 64; d++) {
        float kk[8], ww[8];
        *(float4*)&kk[0] = *(const float4*)&sct[d * 132 + kb];
        *(float4*)&kk[4] = *(const float4*)&sct[d * 132 + kb + 4];
        *(float4*)&ww[0] = *(const float4*)&sw[d * 132 + cb];
        *(float4*)&ww[4] = *(const float4*)&sw[d * 132 + cb + 4];
#pragma unroll
        for (int a = 0; a < 8; a++)
#pragma unroll
            for (int c = 0; c < 8; c++) acc[a][c] = fmaf(kk[a], ww[c], acc[a][c]);
    }

#pragma unroll
    for (int a = 0; a < 8; a++) {
        float* base = L + ((size_t)g * 1024 + k0 + kb + a) * 256 + co0 + cb;
        *(float4*)base = *(float4*)&acc[a][0];
        *(float4*)(base + 4) = *(float4*)&acc[a][4];
    }
}

// ------- logits gather (+ fused final loss in trailing block) ---------------
__global__ __launch_bounds__(256)
void glogits_kernel(const float* __restrict__ outA, const float* __restrict__ L,
                    const float* __restrict__ head_b, float* __restrict__ outB,
                    const float* __restrict__ partial, float* __restrict__ outLoss) {
    const int tid = threadIdx.x;

    if (blockIdx.x == 1024) {
        __shared__ float s[256];
        float v = 0.f;
        for (int i = tid; i < 2048; i += 256) v += partial[i];
        s[tid] = v;
        __syncthreads();
        for (int k = 128; k > 0; k >>= 1) {
            if (tid < k) s[tid] += s[tid + k];
            __syncthreads();
        }
        if (tid == 0) outLoss[0] = s[0] * (1.f / (8.f * 4096.f * 64.f));
        return;
    }

    __shared__ int sidx[32][8];
    const int tt0 = blockIdx.x * 32;
    {
        int tk = tid >> 3, g = tid & 7;
        int tt = tt0 + tk, b = tt >> 12, t = tt & 4095;
        sidx[tk][g] = (int)outA[((size_t)(b * 8 + g)) * TLEN + t];
    }
    __syncthreads();

    const int tok = tid >> 3, vc = tid & 7;
    const int tt = tt0 + tok, b = tt >> 12, t = tt & 4095;
    const int h = vc >> 1, v0 = (vc & 1) * 32;

    float acc[32];
    const float* bp = head_b + h * 64 + v0;
#pragma unroll
    for (int j = 0; j < 8; j++) *(float4*)&acc[j * 4] = *(const float4*)&bp[j * 4];

#pragma unroll
    for (int g = 0; g < 8; g++) {
        const float* Lr = L + ((size_t)(g << 10) + sidx[tok][g]) * 256 + vc * 32;
#pragma unroll
        for (int j = 0; j < 8; j++) {
            float4 lv = *(const float4*)&Lr[j * 4];
            acc[j * 4] += lv.x; acc[j * 4 + 1] += lv.y;
            acc[j * 4 + 2] += lv.z; acc[j * 4 + 3] += lv.w;
        }
    }

    float* op = outB + (((size_t)(b * 4 + h)) * TLEN + t) * 64 + v0;
#pragma unroll
    for (int j = 0; j < 8; j++) *(float4*)&op[j * 4] = *(const float4*)&acc[j * 4];
}

// ------ conv1+conv2 fused (proven, bitwise x1 math) ---------------
#define C12_XROW 136
#define C12_AUD 0
#define C12_W1 144
#define C12_B1 (144 + 448)
#define C12_X1 (144 + 448 + 64)
#define C12_WS (C12_X1 + 64 * C12_XROW)
#define C12_FLOATS (C12_WS + 3 * 5120)
#define C12_BYTES (C12_FLOATS * 4)

__global__ __launch_bounds__(256, 2)
void conv12_kernel(const float* __restrict__ audio, const float* __restrict__ w1,
                   const float* __restrict__ b1, const float* __restrict__ wT,
                   const float* __restrict__ bias, float* __restrict__ y) {
    constexpr int K = 5, COUT = 128, CI_CHUNK = 8;
    constexpr int NX = 12, NXF4 = 3;
    constexpr int WS_FL = CI_CHUNK * K * 128;
    constexpr int NCHUNK = 8;

    extern __shared__ float smem[];
    const uint32_t sb = smem_u32(smem);
    float* audio_s = smem + C12_AUD;
    float* w1s = smem + C12_W1;
    float* b1s = smem + C12_B1;
    float* x1s = smem + C12_X1;

    const int b = blockIdx.z, t0 = blockIdx.x * 128;
    const int tid = threadIdx.x;
    const int tx = tid & 15, ty = tid >> 4;
    const int tb = tx * 8, cb = ty * 8;

    auto loadW = [&](int c, int st) {
        uint32_t wbB = sb + (uint32_t)(C12_WS + st * WS_FL) * 4u;
        const int ci0 = c * CI_CHUNK;
        for (int i4 = tid * 4; i4 < WS_FL; i4 += 1024) {
            int cc = i4 / (K * 128);
            int rem = i4 % (K * 128);
            int j = rem / 128, co = rem % 128;
            cp16(wbB + (uint32_t)i4 * 4u,
                 wT + ((size_t)(ci0 + cc) * K + j) * COUT + co);
        }
        CP_COMMIT();
    };

    for (int i = tid; i < 138; i += 256) {
        int t = t0 - 10 + i;
        cp4(sb + (uint32_t)(C12_AUD + i) * 4u,
            audio + (size_t)b * TLEN + (t >= 0 ? t : 0), t >= 0);
    }
    for (int i4 = tid * 4; i4 < 448; i4 += 1024)
        cp16(sb + (uint32_t)(C12_W1 + i4) * 4u, w1 + i4);
    if (tid < 16)
        cp16(sb + (uint32_t)(C12_B1 + tid * 4) * 4u, b1 + tid * 4);
    CP_COMMIT();
    loadW(0, 0);
    loadW(1, 1);

    CP_WAIT(2);
    __syncthreads();

    for (int i = tid; i < 64 * 132; i += 256) {
        int ch = i / 132, p = i % 132;
        int t = t0 - 4 + p;
        float v = 0.f;
        if (t >= 0) {
            float acc = b1s[ch];
#pragma unroll
            for (int j = 0; j < 7; j++) acc += w1s[ch * 7 + j] * audio_s[p + j];
            v = acc > 0.f ? acc : expm1f(acc);
        }
        x1s[ch * C12_XROW + swzf(p)] = v;
    }
    __syncthreads();

    ull acc2[4][8];
#pragma unroll
    for (int rp = 0; rp < 4; rp++) {
        ull bb2;
        PACK2(bb2, bias[cb + 2 * rp], bias[cb + 2 * rp + 1]);
#pragma unroll
        for (int lt = 0; lt < 8; lt++) acc2[rp][lt] = bb2;
    }

    int st = 0;
#pragma unroll 1
    for (int c = 0; c < NCHUNK; c++) {
        if (c + 1 < NCHUNK) { CP_WAIT(1); } else { CP_WAIT(0); }
        __syncthreads();
        if (c + 2 < NCHUNK) {
            int st2 = st + 2; if (st2 >= 3) st2 -= 3;
            loadW(c + 2, st2);
        }
        const float* wsb = smem + C12_WS + st * WS_FL;
        const float* xbase = x1s + c * CI_CHUNK * C12_XROW;
#pragma unroll 1
        for (int cc = 0; cc < CI_CHUNK; cc++) {
            const float* xrow = xbase + cc * C12_XROW;
            float xv[NXF4 * 4];
#pragma unroll
            for (int q = 0; q < NXF4; q++)
                *(float4*)&xv[q * 4] = *(const float4*)&xrow[swz(tx * 2 + q) << 2];
            ull xb[NX];
#pragma unroll
            for (int p = 0; p < NX; p++) PACKB(xb[p], xv[p]);
#pragma unroll
            for (int j = 0; j < K; j++) {
                const float* wrow = wsb + (cc * K + j) * 128 + cb;
                ulonglong2 w01 = *(const ulonglong2*)&wrow[0];
                ulonglong2 w23 = *(const ulonglong2*)&wrow[4];
                ull wp[4] = {w01.x, w01.y, w23.x, w23.y};
#pragma unroll
                for (int rp = 0; rp < 4; rp++)
#pragma unroll
                    for (int lt = 0; lt < 8; lt++)
                        FMA2(acc2[rp][lt], wp[rp], xb[lt + j]);
            }
        }
        if (++st == 3) st = 0;
    }

    float accs[8][8];
#pragma unroll
    for (int rp = 0; rp < 4; rp++)
#pragma unroll
        for (int lt = 0; lt < 8; lt++)
            UNPACK2(accs[2 * rp][lt], accs[2 * rp + 1][lt], acc2[rp][lt]);

#pragma unroll
    for (int r = 0; r < 8; r++) {
        float o[8];
#pragma unroll
        for (int lt = 0; lt < 8; lt++) {
            float a = accs[r][lt];
            o[lt] = a > 0.f ? a : expm1f(a);
        }
        float* base = &y[((size_t)b * COUT + cb + r) * TLEN + t0 + tb];
        *(float4*)base = *(float4*)&o[0];
        *(float4*)(base + 4) = *(float4*)&o[4];
    }
}

// ---- conv-as-GEMM (proven round 16) ----
template <int CIN, int COUT, int K, int CI_CHUNK, int ELU, int IN_PAD, int OUT_PAD>
__global__ __launch_bounds__(256, 2)
void conv_gemm(const float* __restrict__ x, const float* __restrict__ wT,
               const float* __restrict__ bias, float* __restrict__ y) {
    constexpr int XROW = 136;
    constexpr int NX = 8 + K - 1;
    constexpr int NXF4 = (NX + 3) / 4;
    constexpr int XS_FL = CI_CHUNK * XROW;
    constexpr int WS_FL = CI_CHUNK * K * 128;
    constexpr int STG_FL = XS_FL + WS_FL;
    constexpr int NCHUNK = CIN / CI_CHUNK;
    constexpr int IN_TS = IN_PAD ? TSP : TLEN;
    constexpr int OUT_TS = OUT_PAD ? TSP : TLEN;
    constexpr int NQ = IN_PAD ? 33 : 34;

    extern __shared__ float smem[];
    const uint32_t sb = smem_u32(smem);
    const int b = blockIdx.z, t0 = blockIdx.x * 128, co0 = blockIdx.y * 128;
    const int tid = threadIdx.x;
    const int tx = tid & 15, ty = tid >> 4;
    const int tb = tx * 8, cb = ty * 8;

    auto load_chunk = [&](int c, int st) {
        const int ci0 = c * CI_CHUNK;
        uint32_t xbB = sb + (uint32_t)(st * STG_FL) * 4u;
        for (int i = tid; i < CI_CHUNK * NQ; i += 256) {
            int cc = i / NQ, q = i % NQ;
            uint32_t dst = xbB + (uint32_t)(cc * XROW + (swz(q) << 2)) * 4u;
            if (IN_PAD) {
                cp16(dst, x + (size_t)(b * CIN + ci0 + cc) * IN_TS + t0 + q * 4);
            } else {
                int t = t0 - (K - 1) + q * 4;
                bool ok = (t >= 0) && (t < TLEN);
                cp16z(dst, x + (size_t)(b * CIN + ci0 + cc) * TLEN + (ok ? t : 0), ok);
            }
        }
        uint32_t wbB = xbB + (uint32_t)XS_FL * 4u;
        for (int i4 = tid * 4; i4 < WS_FL; i4 += 1024) {
            int cc = i4 / (K * 128);
            int rem = i4 % (K * 128);
            int j = rem / 128, co = rem % 128;
            cp16(wbB + (uint32_t)i4 * 4u,
                 wT + ((size_t)(ci0 + cc) * K + j) * COUT + co0 + co);
        }
        CP_COMMIT();
    };

    load_chunk(0, 0);
    if (NCHUNK > 1) load_chunk(1, 1);

    ull acc2[4][8];
#pragma unroll
    for (int rp = 0; rp < 4; rp++) {
        ull bb2;
        PACK2(bb2, bias[co0 + cb + 2 * rp], bias[co0 + cb + 2 * rp + 1]);
#pragma unroll
        for (int lt = 0; lt < 8; lt++) acc2[rp][lt] = bb2;
    }

    int st = 0;
#pragma unroll 1
    for (int c = 0; c < NCHUNK; c++) {
        if (c + 1 < NCHUNK) { CP_WAIT(1); } else { CP_WAIT(0); }
        __syncthreads();
        if (c + 2 < NCHUNK) {
            int st2 = st + 2; if (st2 >= 3) st2 -= 3;
            load_chunk(c + 2, st2);
        }
        const float* xsb = smem + st * STG_FL;
        const float* wsb = xsb + XS_FL;
#pragma unroll 1
        for (int cc = 0; cc < CI_CHUNK; cc++) {
            const float* xrow = xsb + cc * XROW;
            float xv[NXF4 * 4];
#pragma unroll
            for (int q = 0; q < NXF4; q++)
                *(float4*)&xv[q * 4] = *(const float4*)&xrow[swz(tx * 2 + q) << 2];
            ull xb[NX];
#pragma unroll
            for (int p = 0; p < NX; p++) PACKB(xb[p], xv[p]);
#pragma unroll
            for (int j = 0; j < K; j++) {
                const float* wrow = wsb + (cc * K + j) * 128 + cb;
                ulonglong2 w01 = *(const ulonglong2*)&wrow[0];
                ulonglong2 w23 = *(const ulonglong2*)&wrow[4];
                ull wp[4] = {w01.x, w01.y, w23.x, w23.y};
#pragma unroll
                for (int rp = 0; rp < 4; rp++)
#pragma unroll
                    for (int lt = 0; lt < 8; lt++)
                        FMA2(acc2[rp][lt], wp[rp], xb[lt + j]);
            }
        }
        if (++st == 3) st = 0;
    }

    float accs[8][8];
#pragma unroll
    for (int rp = 0; rp < 4; rp++)
#pragma unroll
        for (int lt = 0; lt < 8; lt++)
            UNPACK2(accs[2 * rp][lt], accs[2 * rp + 1][lt], acc2[rp][lt]);

#pragma unroll
    for (int r = 0; r < 8; r++) {
        float o[8];
#pragma unroll
        for (int lt = 0; lt < 8; lt++) {
            float a = accs[r][lt];
            if (ELU) a = a > 0.f ? a : expm1f(a);
            o[lt] = a;
        }
        if (OUT_PAD) {
            float* base = &y[(size_t)(b * COUT + co0 + cb + r) * OUT_TS + 2 + t0 + tb];
#pragma unroll
            for (int h = 0; h < 4; h++)
                *(float2*)(base + 2 * h) = make_float2(o[2 * h], o[2 * h + 1]);
        } else {
            float* base = &y[(size_t)(b * COUT + co0 + cb + r) * OUT_TS + t0 + tb];
            *(float4*)base = *(float4*)&o[0];
            *(float4*)(base + 4) = *(float4*)&o[4];
        }
    }
}

// ---------- VQ v3: dp4a int8 coarse + exact fp32 refine ----------
// smem float offsets
#define V3_ZT 0
#define V3_ZQ8 8192
#define V3_C8A 10240
#define V3_C8B 12288
#define V3_CSCA 14336
#define V3_CSCB 14464
#define V3_CN 14592
#define V3_ZN 15616
#define V3_SZ 15744
#define V3_BAND 15872
#define V3_RMIN 16000
#define V3_CNT 16128
#define V3_CAND 16256
#define V3_OVFN 18304
#define V3_OVFL 18308
#define V3_FLOATS 18440
#define V3_BYTES (V3_FLOATS * 4)
#define CAP3 16
// aliases (dead regions after their phases)
#define V3_BI V3_RMIN
#define V3_REDV V3_CAND
#define V3_REDI (V3_CAND + 256)
#define V3_LS V3_CAND

__global__ __launch_bounds__(256, 2)
void vq_kernel(const float* __restrict__ x5, const float* __restrict__ cbk,
               const float* __restrict__ cnormG, const int* __restrict__ cb8,
               const float* __restrict__ cscG, const float* __restrict__ gs,
               float* __restrict__ out_a, float* __restrict__ partial) {
    extern __shared__ float smem[];
    const uint32_t sb = smem_u32(smem);
    float* ztT = smem + V3_ZT;
    int* zq8 = (int*)(smem + V3_ZQ8);
    float* cnormS = smem + V3_CN;
    float* znorm = smem + V3_ZN;
    float* szS = smem + V3_SZ;
    float* band = smem + V3_BAND;
    unsigned* runmin = (unsigned*)(smem + V3_RMIN);
    int* cnt = (int*)(smem + V3_CNT);
    int* cand = (int*)(smem + V3_CAND);
    int* ovfn = (int*)(smem + V3_OVFN);
    int* ovfl = (int*)(smem + V3_OVFL);
    int* besti = (int*)(smem + V3_BI);
    float* redv = smem + V3_REDV;
    int* redi = (int*)(smem + V3_REDI);
    float* lscr = smem + V3_LS;

    const int b = blockIdx.z, g = blockIdx.y;
    const int t0 = blockIdx.x * 128;
    const int tid = threadIdx.x;
    const int tx = tid & 15, ty = tid >> 4;
    const int trow = tx * 8, cbase = ty * 8;

    const float Amax = __ldg(&gs[g * 4]);
    const float scmax = __ldg(&gs[g * 4 + 1]);
    const float cnmax = __ldg(&gs[g * 4 + 2]);

    auto loadC = [&](int c, int bf) {
        uint32_t cB = sb + (uint32_t)(bf ? V3_C8B : V3_C8A) * 4u;
        const int* src = cb8 + ((g * 8 + c) << 11);      // 16*128 ints
        for (int i = tid; i < 512; i += 256)
            cp16(cB + (uint32_t)i * 16u, src + i * 4);
        if (tid < 32)
            cp16(sb + (uint32_t)((bf ? V3_CSCB : V3_CSCA) + tid * 4) * 4u,
                 cscG + g * 1024 + (c << 7) + tid * 4);
        CP_COMMIT();
    };

    // entry: z tile fp32 + full cnorm + chunk 0
    for (int i = tid; i < 2048; i += 256) {
        int d = i >> 5, ch = i & 31;
        cp16(sb + (uint32_t)(V3_ZT + d * 128 + (swz(ch) << 2)) * 4u,
             x5 + (((size_t)b * 512) + (g << 6) + d) * TLEN + t0 + ch * 4);
    }
    cp16(sb + (uint32_t)(V3_CN + tid * 4) * 4u, cnormG + g * 1024 + tid * 4);
    loadC(0, 0);

    float zn[8], szr[8];

#pragma unroll 1
    for (int c = 0; c < 8; c++) {
        const int k0 = c << 7;
        if (c + 1 < 8) { loadC(c + 1, (c + 1) & 1); CP_WAIT(1); } else { CP_WAIT(0); }
        __syncthreads();

        if (c == 0) {
            // per-token: norm (exact chain), max, int8 quantize, band, init
            if (tid < 128) {
                int off = swzf(tid);
                float s = 0.f, M = 0.f;
#pragma unroll 8
                for (int d = 0; d < 64; d++) {
                    float v = ztT[d * 128 + off];
                    s += v * v;                     // ascending-d, matches proven order
                    M = fmaxf(M, fabsf(v));
                }
                znorm[tid] = s;
                float Msafe = fmaxf(M, 1e-30f);
                float szv = Msafe / 127.f;
                float inv = 127.f / Msafe;
                szS[tid] = szv;
                int L1 = 0;
#pragma unroll
                for (int dq = 0; dq < 16; dq++) {
                    int p = 0;
#pragma unroll
                    for (int j = 0; j < 4; j++) {
                        int q = __float2int_rn(ztT[(dq * 4 + j) * 128 + off] * inv);
                        q = q > 127 ? 127 : (q < -127 ? -127 : q);
                        L1 += (q < 0 ? -q : q);
                        p |= (q & 0xFF) << (8 * j);
                    }
                    zq8[dq * 128 + tid] = p;
                }
                band[tid] = szv * (Amax + scmax * (float)L1) * 1.0001f
                            + 1e-5f * (s + cnmax);
                runmin[tid] = 0xFF800000u;          // enc(+inf)
                cnt[tid] = 0;
            }
            if (tid == 0) *ovfn = 0;
            __syncthreads();
#pragma unroll
            for (int a = 0; a < 8; a++) { zn[a] = znorm[trow + a]; szr[a] = szS[trow + a]; }
        }

        const int* c8 = (const int*)(smem + ((c & 1) ? V3_C8B : V3_C8A));
        const float* scv = smem + ((c & 1) ? V3_CSCB : V3_CSCA);

        int idot[8][8];
#pragma unroll
        for (int a = 0; a < 8; a++)
#pragma unroll
            for (int q = 0; q < 8; q++) idot[a][q] = 0;

#pragma unroll
        for (int dq = 0; dq < 16; dq++) {
            int4 z0 = *(const int4*)&zq8[dq * 128 + trow];
            int4 z1 = *(const int4*)&zq8[dq * 128 + trow + 4];
            int4 c0 = *(const int4*)&c8[dq * 128 + cbase];
            int4 c1 = *(const int4*)&c8[dq * 128 + cbase + 4];
            int zzv[8] = {z0.x, z0.y, z0.z, z0.w, z1.x, z1.y, z1.z, z1.w};
            int ccv[8] = {c0.x, c0.y, c0.z, c0.w, c1.x, c1.y, c1.z, c1.w};
#pragma unroll
            for (int a = 0; a < 8; a++)
#pragma unroll
                for (int q = 0; q < 8; q++)
                    idot[a][q] = __dp4a(zzv[a], ccv[q], idot[a][q]);
        }

        float scr[8], cnr[8];
#pragma unroll
        for (int q = 0; q < 8; q++) {
            scr[q] = scv[cbase + q];
            cnr[q] = cnormS[k0 + cbase + q];
        }

        // phase 1: token minima -> atomicMin
#pragma unroll
        for (int a = 0; a < 8; a++) {
            float m = 3.4e38f;
#pragma unroll
            for (int q = 0; q < 8; q++) {
                float dh = fmaf(-2.f * szr[a] * scr[q], (float)idot[a][q], zn[a] + cnr[q]);
                m = fminf(m, dh);
            }
            atomicMin(&runmin[trow + a], encf(m));
        }
        __syncthreads();

        // phase 2: candidate collection (superset: runmin only decreases later)
#pragma unroll
        for (int a = 0; a < 8; a++) {
            float th = decf(runmin[trow + a]) + band[trow + a];
#pragma unroll
            for (int q = 0; q < 8; q++) {
                float dh = fmaf(-2.f * szr[a] * scr[q], (float)idot[a][q], zn[a] + cnr[q]);
                if (dh <= th) {
                    int s = atomicAdd(&cnt[trow + a], 1);
                    if (s < CAP3) cand[(trow + a) * CAP3 + s] = k0 + cbase + q;
                }
            }
        }
        __syncthreads();
    }

    // exact refine: fp32 fmaf chain, d ascending == proven FMA2 per-lane order
    if (tid < 128) {
        int n = cnt[tid];
        if (n <= CAP3) {
            int off = swzf(tid);
            float best = 3.4e38f;
            int bidx = 1 << 30;
            for (int s = 0; s < n; s++) {
                int k = cand[tid * CAP3 + s];
                const float* cr = cbk + ((size_t)g * 1024 + k) * 64;
                float acc = 0.f;
#pragma unroll 8
                for (int d = 0; d < 64; d++) acc = fmaf(ztT[d * 128 + off], cr[d], acc);
                float dist = znorm[tid] + cnormS[k] - 2.f * acc;
                if (dist < best || (dist == best && k < bidx)) { best = dist; bidx = k; }
            }
            besti[tid] = bidx;     // besti aliases runmin (no longer read)
        } else {
            int o = atomicAdd(ovfn, 1);
            ovfl[o] = tid;
        }
    }
    __syncthreads();

    // rare fallback: block-cooperative exact full scan (cand dead -> redv/redi)
    int novf = *ovfn;
    for (int o = 0; o < novf; o++) {
        int t = ovfl[o];
        int off = swzf(t);
        float best = 3.4e38f;
        int bidx = 1 << 30;
        for (int k = tid; k < 1024; k += 256) {
            const float* cr = cbk + ((size_t)g * 1024 + k) * 64;
            float acc = 0.f;
#pragma unroll 8
            for (int d = 0; d < 64; d++) acc = fmaf(ztT[d * 128 + off], cr[d], acc);
            float dist = znorm[t] + cnormS[k] - 2.f * acc;
            if (dist < best || (dist == best && k < bidx)) { best = dist; bidx = k; }
        }
        redv[tid] = best; redi[tid] = bidx;
        __syncthreads();
        for (int s = 128; s > 0; s >>= 1) {
            if (tid < s) {
                float v = redv[tid + s]; int ii = redi[tid + s];
                if (v < redv[tid] || (v == redv[tid] && ii < redi[tid])) {
                    redv[tid] = v; redi[tid] = ii;
                }
            }
            __syncthreads();
        }
        if (tid == 0) besti[t] = redi[0];
        __syncthreads();
    }

    if (tid < 128)
        out_a[((size_t)b * 8 + g) * TLEN + t0 + tid] = (float)besti[tid];
    __syncthreads();

    // exact loss (lscr aliases cand, dead)
    float ls = 0.f;
    for (int i = tid; i < 64 * 128; i += 256) {
        int d = i & 63, lt = i >> 6;
        float qv = cbk[((size_t)g * 1024 + besti[lt]) * 64 + d];
        float df = qv - ztT[d * 128 + swzf(lt)];
        ls += df * df;
    }
    __syncthreads();
    lscr[tid] = ls;
    __syncthreads();
    for (int s = 128; s > 0; s >>= 1) {
        if (tid < s) lscr[tid] += lscr[tid + s];
        __syncthreads();
    }
    if (tid == 0)
        partial[((size_t)b * 8 + g) * 32 + blockIdx.x] = lscr[0];
}

// ---------------- launch ----------------
extern "C" void kernel_launch(void* const* d_in, const int* in_sizes, int n_in,
                              void* d_out, int out_size) {
    const float* audio = (const float*)d_in[0];
    const float* w1 = (const float*)d_in[1];
    const float* b1 = (const float*)d_in[2];
    const float* w2 = (const float*)d_in[3];
    const float* b2 = (const float*)d_in[4];
    const float* w3 = (const float*)d_in[5];
    const float* b3 = (const float*)d_in[6];
    const float* w4 = (const float*)d_in[7];
    const float* b4 = (const float*)d_in[8];
    const float* w5 = (const float*)d_in[9];
    const float* b5 = (const float*)d_in[10];
    const float* codebooks = (const float*)d_in[11];
    const float* head_w = (const float*)d_in[12];
    const float* head_b = (const float*)d_in[13];
    float* out = (float*)d_out;

    float *x2, *x3p, *x4p, *x5, *w2T, *w3T, *w4T, *w5T, *hwT, *cnm, *csc, *cA, *gsV, *Lt, *part;
    int* cb8;
    cudaGetSymbolAddress((void**)&x2, g_x2);
    cudaGetSymbolAddress((void**)&x3p, g_x3p);
    cudaGetSymbolAddress((void**)&x4p, g_x4p);
    cudaGetSymbolAddress((void**)&x5, g_x5);
    cudaGetSymbolAddress((void**)&w2T, g_w2T);
    cudaGetSymbolAddress((void**)&w3T, g_w3T);
    cudaGetSymbolAddress((void**)&w4T, g_w4T);
    cudaGetSymbolAddress((void**)&w5T, g_w5T);
    cudaGetSymbolAddress((void**)&hwT, g_hwT);
    cudaGetSymbolAddress((void**)&cnm, g_cnorm);
    cudaGetSymbolAddress((void**)&cb8, g_cb8);
    cudaGetSymbolAddress((void**)&csc, g_csc);
    cudaGetSymbolAddress((void**)&cA, g_cA);
    cudaGetSymbolAddress((void**)&gsV, g_gstat);
    cudaGetSymbolAddress((void**)&Lt, g_L);
    cudaGetSymbolAddress((void**)&part, g_part);

    const int SM_C3 = (3 * (8 * 136 + 8 * 5 * 128)) * 4;
    const int SM_C4 = (3 * (16 * 136 + 16 * 3 * 128)) * 4;
    const int SM_C5 = SM_C4;
    const int SM_CL = (2 * 64 * 132) * 4;

    cudaFuncSetAttribute((const void*)conv12_kernel,
                         cudaFuncAttributeMaxDynamicSharedMemorySize, C12_BYTES);
    cudaFuncSetAttribute((const void*)conv_gemm<128, 256, 5, 8, 1, 0, 1>,
                         cudaFuncAttributeMaxDynamicSharedMemorySize, SM_C3);
    cudaFuncSetAttribute((const void*)conv_gemm<256, 512, 3, 16, 1, 1, 1>,
                         cudaFuncAttributeMaxDynamicSharedMemorySize, SM_C4);
    cudaFuncSetAttribute((const void*)conv_gemm<512, 512, 3, 16, 0, 1, 0>,
                         cudaFuncAttributeMaxDynamicSharedMemorySize, SM_C5);
    cudaFuncSetAttribute((const void*)codelogits_kernel,
                         cudaFuncAttributeMaxDynamicSharedMemorySize, SM_CL);
    cudaFuncSetAttribute((const void*)vq_kernel,
                         cudaFuncAttributeMaxDynamicSharedMemorySize, V3_BYTES);

    prep_kernel<<<(N_PREP + 255) / 256, 256>>>(w2, w3, w4, w5, head_w, codebooks,
                                               w2T, w3T, w4T, w5T, hwT, cnm,
                                               x3p, x4p);
    gstat_kernel<<<8, 256>>>(cA, csc, cnm, gsV);
    codelogits_kernel<<<dim3(8, 2, 8), 256, SM_CL>>>(codebooks, hwT, Lt);

    conv12_kernel<<<dim3(32, 1, 8), 256, C12_BYTES>>>(audio, w1, b1, w2T, b2, x2);
    conv_gemm<128, 256, 5, 8, 1, 0, 1><<<dim3(32, 2, 8), 256, SM_C3>>>(x2, w3T, b3, x3p);
    conv_gemm<256, 512, 3, 16, 1, 1, 1><<<dim3(32, 4, 8), 256, SM_C4>>>(x3p, w4T, b4, x4p);
    conv_gemm<512, 512, 3, 16, 0, 1, 0><<<dim3(32, 4, 8), 256, SM_C5>>>(x4p, w5T, b5, x5);

    vq_kernel<<<dim3(32, 8, 8), 256, V3_BYTES>>>(x5, codebooks, cnm, cb8, csc, gsV,
                                                 out + OFF_A, part);
    glogits_kernel<<<1025, 256>>>(out + OFF_A, Lt, head_b, out + OFF_B,
                                  part, out + OFF_L);
}